// round 1
// baseline (speedup 1.0000x reference)
#include <cuda_runtime.h>

#define Bsz 8192
#define Dd  512
#define Ww  8
#define XS  8704           // 17*512 row stride of x and out
#define KT  16
#define MT  32
#define GB  (Bsz/MT)       // 256 blocks along batch

enum { M_STORE=0, M_DOT=1, M_NORM=2, M_NORM_RES=3 };

// ---- scratch (allocation-free rule: __device__ globals) ----
__device__ float s_q [Bsz*Dd];
__device__ float s_kc[Bsz*Dd];
__device__ float s_v [Bsz*Dd];
__device__ float s_ap[Bsz*Ww];
__device__ float s_an[Bsz*Ww];

// ---- packed f32x2 helpers (sm_103a FFMA2 path: 2x scalar FFMA throughput) ----
__device__ __forceinline__ unsigned long long pack2(float lo, float hi){
  unsigned long long r;
  asm("mov.b64 %0, {%1, %2};" : "=l"(r)
      : "r"(__float_as_uint(lo)), "r"(__float_as_uint(hi)));
  return r;
}
__device__ __forceinline__ void unpack2(unsigned long long v, float &lo, float &hi){
  unsigned int l, h;
  asm("mov.b64 {%0, %1}, %2;" : "=r"(l), "=r"(h) : "l"(v));
  lo = __uint_as_float(l); hi = __uint_as_float(h);
}
__device__ __forceinline__ void ffma2(unsigned long long &c,
                                      unsigned long long a, unsigned long long b){
  asm("fma.rn.f32x2 %0, %1, %2, %0;" : "+l"(c) : "l"(a), "l"(b));
}

// =======================================================================
// NT GEMM: C[m,e] = sum_k A[m,k] * Wt[e,k] (+bias[e]), M-tile=32, N=512 full.
// Per-z batch offsets: A += z*aZ, Wt += z*512*512, bias += z*512, out += z*oZ.
// MODE_STORE   : store C to out (ldo)
// MODE_DOT     : dotOut[b*8+z] = sum_e Q[b,e]*C[b,e]    (kp/kn path, no C store)
// MODE_NORM    : out = l2norm_row(C)                    (fp/fn path)
// MODE_NORM_RES: out = l2norm_row(C + R)                (fc path)
// =======================================================================
template<int MODE>
__global__ __launch_bounds__(256,2) void gemm512(
    const float* __restrict__ A, int lda, int aZ,
    const float* __restrict__ Wt, const float* __restrict__ bias,
    float* out, int ldo, int oZ,
    const float* __restrict__ Q,
    const float* __restrict__ R, int ldr,
    float* __restrict__ dotOut)
{
  const int z = blockIdx.z;
  A    += (size_t)z * aZ;
  Wt   += (size_t)z * (Dd*Dd);
  bias += (size_t)z * Dd;
  if (out) out += (size_t)z * oZ;

  const int tid   = threadIdx.x;
  const int cg    = tid & 63;     // col group: cols {2cg+128p, 2cg+128p+1}
  const int rg    = tid >> 6;     // row group 0..3
  const int r0    = rg * 8;
  const int bBase = blockIdx.x * MT;

  __shared__ __align__(16) float Ws[KT*Dd];   // [k][e]  (transposed on store)
  __shared__ __align__(16) float As[KT*36];   // [k][m], padded row 36
  __shared__ float red[8][8];
  __shared__ float sScale[MT];

  unsigned long long acc[8][4];
  #pragma unroll
  for (int r=0;r<8;r++)
    #pragma unroll
    for (int p=0;p<4;p++) acc[r][p] = 0ull;

  const float* aBase = A + (size_t)bBase * lda;
  const int lm = tid >> 2, lc = tid & 3;      // A-tile loader mapping (tid<128)

  float4 wbuf[8]; float4 abuf;
  // prologue loads (k0 = 0)
  #pragma unroll
  for (int i=0;i<8;i++){
    int idx = i*256 + tid; int c = idx>>9, n = idx&511;
    wbuf[i] = *(const float4*)(Wt + (size_t)n*Dd + c*4);
  }
  if (tid < 128) abuf = *(const float4*)(aBase + (size_t)lm*lda + lc*4);

  for (int k0 = 0; k0 < Dd; k0 += KT){
    __syncthreads();
    // stage (transpose) to smem
    #pragma unroll
    for (int i=0;i<8;i++){
      int idx = i*256 + tid; int c = idx>>9, n = idx&511;
      Ws[(c*4+0)*Dd + n] = wbuf[i].x;
      Ws[(c*4+1)*Dd + n] = wbuf[i].y;
      Ws[(c*4+2)*Dd + n] = wbuf[i].z;
      Ws[(c*4+3)*Dd + n] = wbuf[i].w;
    }
    if (tid < 128){
      As[(lc*4+0)*36 + lm] = abuf.x;
      As[(lc*4+1)*36 + lm] = abuf.y;
      As[(lc*4+2)*36 + lm] = abuf.z;
      As[(lc*4+3)*36 + lm] = abuf.w;
    }
    __syncthreads();
    // prefetch next chunk (LDG issued before compute, latency hidden)
    const int knext = k0 + KT;
    if (knext < Dd){
      #pragma unroll
      for (int i=0;i<8;i++){
        int idx = i*256 + tid; int c = idx>>9, n = idx&511;
        wbuf[i] = *(const float4*)(Wt + (size_t)n*Dd + knext + c*4);
      }
      if (tid < 128) abuf = *(const float4*)(aBase + (size_t)lm*lda + knext + lc*4);
    }
    // compute
    #pragma unroll 8
    for (int k=0;k<KT;k++){
      const unsigned long long* wu = (const unsigned long long*)(Ws + k*Dd);
      const float* ar = As + k*36 + r0;
      float4 a0 = *(const float4*)(ar);
      float4 a1 = *(const float4*)(ar + 4);
      unsigned long long wp[4];
      wp[0]=wu[cg]; wp[1]=wu[cg+64]; wp[2]=wu[cg+128]; wp[3]=wu[cg+192];
      unsigned long long ad[8];
      ad[0]=pack2(a0.x,a0.x); ad[1]=pack2(a0.y,a0.y);
      ad[2]=pack2(a0.z,a0.z); ad[3]=pack2(a0.w,a0.w);
      ad[4]=pack2(a1.x,a1.x); ad[5]=pack2(a1.y,a1.y);
      ad[6]=pack2(a1.z,a1.z); ad[7]=pack2(a1.w,a1.w);
      #pragma unroll
      for (int r=0;r<8;r++)
        #pragma unroll
        for (int p=0;p<4;p++) ffma2(acc[r][p], ad[r], wp[p]);
    }
  }

  // ---------------- epilogue ----------------
  float2 bias2[4];
  #pragma unroll
  for (int p=0;p<4;p++) bias2[p] = *(const float2*)(bias + 2*cg + 128*p);

  if constexpr (MODE == M_STORE){
    #pragma unroll
    for (int r=0;r<8;r++){
      float* orow = out + (size_t)(bBase + r0 + r)*ldo + 2*cg;
      #pragma unroll
      for (int p=0;p<4;p++){
        float lo,hi; unpack2(acc[r][p], lo, hi);
        float2 v; v.x = lo + bias2[p].x; v.y = hi + bias2[p].y;
        *(float2*)(orow + 128*p) = v;
      }
    }
  }
  else if constexpr (MODE == M_DOT){
    float part[8];
    #pragma unroll
    for (int r=0;r<8;r++){
      part[r] = 0.f;
      const float* qrow = Q + (size_t)(bBase + r0 + r)*Dd + 2*cg;
      #pragma unroll
      for (int p=0;p<4;p++){
        float lo,hi; unpack2(acc[r][p], lo, hi);
        lo += bias2[p].x; hi += bias2[p].y;
        float2 qq = *(const float2*)(qrow + 128*p);
        part[r] += lo*qq.x + hi*qq.y;
      }
    }
    #pragma unroll
    for (int r=0;r<8;r++){
      float pv = part[r];
      #pragma unroll
      for (int o=16;o;o>>=1) pv += __shfl_xor_sync(0xffffffffu, pv, o);
      if ((tid & 31) == 0) red[tid>>5][r] = pv;
    }
    __syncthreads();
    if (tid < 32){
      float s = red[(tid>>3)*2][tid&7] + red[(tid>>3)*2+1][tid&7];
      dotOut[(size_t)(bBase + tid)*Ww + blockIdx.z] = s;
    }
  }
  else { // M_NORM / M_NORM_RES
    float part[8];
    #pragma unroll
    for (int r=0;r<8;r++){
      part[r] = 0.f;
      const float* rrow = (MODE == M_NORM_RES)
          ? (R + (size_t)(bBase + r0 + r)*ldr + 2*cg) : nullptr;
      #pragma unroll
      for (int p=0;p<4;p++){
        float lo,hi; unpack2(acc[r][p], lo, hi);
        lo += bias2[p].x; hi += bias2[p].y;
        if constexpr (MODE == M_NORM_RES){
          float2 rv = *(const float2*)(rrow + 128*p);
          lo += rv.x; hi += rv.y;
        }
        part[r] += lo*lo + hi*hi;
        acc[r][p] = pack2(lo, hi);
      }
    }
    #pragma unroll
    for (int r=0;r<8;r++){
      float pv = part[r];
      #pragma unroll
      for (int o=16;o;o>>=1) pv += __shfl_xor_sync(0xffffffffu, pv, o);
      if ((tid & 31) == 0) red[tid>>5][r] = pv;
    }
    __syncthreads();
    if (tid < 32){
      float ss = red[(tid>>3)*2][tid&7] + red[(tid>>3)*2+1][tid&7];
      sScale[tid] = 1.f / fmaxf(sqrtf(ss), 1e-12f);
    }
    __syncthreads();
    #pragma unroll
    for (int r=0;r<8;r++){
      float sc = sScale[r0 + r];
      float* orow = out + (size_t)(bBase + r0 + r)*ldo + 2*cg;
      #pragma unroll
      for (int p=0;p<4;p++){
        float lo,hi; unpack2(acc[r][p], lo, hi);
        float2 v; v.x = lo*sc; v.y = hi*sc;
        *(float2*)(orow + 128*p) = v;
      }
    }
  }
}

// =======================================================================
// mix: attn_c = q.kc ; v = l2norm(xc*attn + sum_w ap*xp_w + sum_w an*xn_w)
// one block (128 threads) per batch row; float4 per thread.
// =======================================================================
__global__ void mix_kernel(const float* __restrict__ x, float* __restrict__ outv,
                           const float* __restrict__ q, const float* __restrict__ kc,
                           const float* __restrict__ ap, const float* __restrict__ an)
{
  __shared__ float sb[4];
  const int b = blockIdx.x, t = threadIdx.x;
  const float4* xr = (const float4*)(x + (size_t)b*XS);

  float4 q4 = ((const float4*)(q  + (size_t)b*Dd))[t];
  float4 k4 = ((const float4*)(kc + (size_t)b*Dd))[t];
  float part = q4.x*k4.x + q4.y*k4.y + q4.z*k4.z + q4.w*k4.w;
  #pragma unroll
  for (int o=16;o;o>>=1) part += __shfl_xor_sync(0xffffffffu, part, o);
  if ((t & 31) == 0) sb[t>>5] = part;
  __syncthreads();
  const float attn = sb[0] + sb[1] + sb[2] + sb[3];
  __syncthreads();

  float4 xc4 = xr[1024 + t];
  float4 acc;
  acc.x = xc4.x*attn; acc.y = xc4.y*attn; acc.z = xc4.z*attn; acc.w = xc4.w*attn;
  #pragma unroll
  for (int w=0;w<Ww;w++){
    float aw = ap[(size_t)b*Ww + w];
    float4 p4 = xr[w*128 + t];
    acc.x += aw*p4.x; acc.y += aw*p4.y; acc.z += aw*p4.z; acc.w += aw*p4.w;
    float nw = an[(size_t)b*Ww + w];
    float4 n4 = xr[(9+w)*128 + t];
    acc.x += nw*n4.x; acc.y += nw*n4.y; acc.z += nw*n4.z; acc.w += nw*n4.w;
  }
  float ss = acc.x*acc.x + acc.y*acc.y + acc.z*acc.z + acc.w*acc.w;
  #pragma unroll
  for (int o=16;o;o>>=1) ss += __shfl_xor_sync(0xffffffffu, ss, o);
  if ((t & 31) == 0) sb[t>>5] = ss;
  __syncthreads();
  float tot = sb[0] + sb[1] + sb[2] + sb[3];
  float sc = 1.f / fmaxf(sqrtf(tot), 1e-12f);
  float4 v; v.x = acc.x*sc; v.y = acc.y*sc; v.z = acc.z*sc; v.w = acc.w*sc;
  ((float4*)(outv + (size_t)b*Dd))[t] = v;
}

// =======================================================================
extern "C" void kernel_launch(void* const* d_in, const int* in_sizes, int n_in,
                              void* d_out, int out_size)
{
  const float* x   = (const float*)d_in[0];
  const float* Wq  = (const float*)d_in[1];
  const float* bq  = (const float*)d_in[2];
  const float* Wkc = (const float*)d_in[3];
  const float* bkc = (const float*)d_in[4];
  const float* Wkp = (const float*)d_in[5];
  const float* bkp = (const float*)d_in[6];
  const float* Wkn = (const float*)d_in[7];
  const float* bkn = (const float*)d_in[8];
  const float* Wfp = (const float*)d_in[9];
  const float* bfp = (const float*)d_in[10];
  const float* Wfn = (const float*)d_in[11];
  const float* bfn = (const float*)d_in[12];
  const float* Wfc = (const float*)d_in[13];
  const float* bfc = (const float*)d_in[14];
  float* out = (float*)d_out;

  float *pq, *pkc, *pv, *pap, *pan;
  cudaGetSymbolAddress((void**)&pq,  s_q);
  cudaGetSymbolAddress((void**)&pkc, s_kc);
  cudaGetSymbolAddress((void**)&pv,  s_v);
  cudaGetSymbolAddress((void**)&pap, s_ap);
  cudaGetSymbolAddress((void**)&pan, s_an);

  dim3 blk(256);

  // q = xc @ Wq^T + bq ; kc = xc @ Wkc^T + bkc
  gemm512<M_STORE><<<dim3(GB,1,1), blk>>>(x+4096, XS, 0, Wq,  bq,  pq,  Dd, 0,
                                          nullptr, nullptr, 0, nullptr);
  gemm512<M_STORE><<<dim3(GB,1,1), blk>>>(x+4096, XS, 0, Wkc, bkc, pkc, Dd, 0,
                                          nullptr, nullptr, 0, nullptr);
  // ap[b,w] = q . (xp_w @ Wkp_w^T + bkp_w)  (kp never materialized)
  gemm512<M_DOT><<<dim3(GB,1,Ww), blk>>>(x,      XS, Dd, Wkp, bkp, nullptr, 0, 0,
                                         pq, nullptr, 0, pap);
  gemm512<M_DOT><<<dim3(GB,1,Ww), blk>>>(x+4608, XS, Dd, Wkn, bkn, nullptr, 0, 0,
                                         pq, nullptr, 0, pan);
  // v = l2norm(xc*attn + sum ap*xp + sum an*xn)
  mix_kernel<<<Bsz, 128>>>(x, pv, pq, pkc, pap, pan);
  // xp_out / xn_out = l2norm(xp_w @ Wfp_w^T + bfp_w) -> straight to d_out
  gemm512<M_NORM><<<dim3(GB,1,Ww), blk>>>(x,      XS, Dd, Wfp, bfp, out,      XS, Dd,
                                          nullptr, nullptr, 0, nullptr);
  gemm512<M_NORM><<<dim3(GB,1,Ww), blk>>>(x+4608, XS, Dd, Wfn, bfn, out+4608, XS, Dd,
                                          nullptr, nullptr, 0, nullptr);
  // center: l2norm(v @ Wfc^T + bfc + xc)
  gemm512<M_NORM_RES><<<dim3(GB,1,1), blk>>>(pv, Dd, 0, Wfc, bfc, out+4096, XS, 0,
                                             nullptr, x+4096, XS, nullptr);
}

// round 3
// speedup vs baseline: 3.3154x; 3.3154x over previous
#include <cuda_runtime.h>
#include <cuda_bf16.h>
#include <cstdint>

#define Bsz 8192
#define Dd  512
#define XS  8704           // 17*512 row stride of x / out
#define WSZ 262144         // 512*512 per weight matrix
#define NW  35
#define NSTG 24            // 3 terms * 8 k-chunks of 64
#define STG_BYTES 49152    // A 32KB + B 16KB per stage
#define DYN_SMEM (3*STG_BYTES + 1024)

enum { M_STORE=0, M_DOT=1, M_NORM=2, M_NORM_RES=3 };

// ---------------- device scratch (allocation-free rule) ----------------
__device__ __align__(256) __nv_bfloat16 g_xh[Bsz*XS];
__device__ __align__(256) __nv_bfloat16 g_xl[Bsz*XS];
__device__ __align__(256) __nv_bfloat16 g_wh[NW*WSZ];
__device__ __align__(256) __nv_bfloat16 g_wl[NW*WSZ];
__device__ __align__(256) __nv_bfloat16 g_vh[Bsz*Dd];
__device__ __align__(256) __nv_bfloat16 g_vl[Bsz*Dd];
__device__ __align__(256) float s_qkc[2*Bsz*Dd];     // q then kc
__device__ __align__(256) float s_v[Bsz*Dd];
__device__ __align__(256) float s_dotP[16*Bsz*4];    // [z][b][ctaN]
__device__ __align__(256) float s_nrmP[17*Bsz*4];    // [zi][b][ctaN]

// ---------------- ptx helpers ----------------
__device__ __forceinline__ uint32_t smem_u32(const void* p){
  uint32_t a;
  asm("{ .reg .u64 t; cvta.to.shared.u64 t, %1; cvt.u32.u64 %0, t; }" : "=r"(a) : "l"(p));
  return a;
}
#define CP16(s,g) asm volatile("cp.async.cg.shared.global [%0], [%1], 16;" :: "r"(s), "l"(g))
#define CPCOMMIT() asm volatile("cp.async.commit_group;" ::: "memory")
#define CPWAIT2()  asm volatile("cp.async.wait_group 2;" ::: "memory")

__device__ __forceinline__ void ldsm4(uint32_t* r, uint32_t a){
  asm volatile("ldmatrix.sync.aligned.m8n8.x4.shared.b16 {%0,%1,%2,%3}, [%4];"
    : "=r"(r[0]),"=r"(r[1]),"=r"(r[2]),"=r"(r[3]) : "r"(a));
}
#define MMA(c,a,b0,b1) \
  asm volatile("mma.sync.aligned.m16n8k16.row.col.f32.bf16.bf16.f32 " \
    "{%0,%1,%2,%3},{%4,%5,%6,%7},{%8,%9},{%0,%1,%2,%3};" \
    : "+f"((c)[0]),"+f"((c)[1]),"+f"((c)[2]),"+f"((c)[3]) \
    : "r"((a)[0]),"r"((a)[1]),"r"((a)[2]),"r"((a)[3]),"r"(b0),"r"(b1))

// ---------------- fp32 -> bf16 hi/lo split ----------------
__global__ void cvt8(const float* __restrict__ s, __nv_bfloat16* __restrict__ h,
                     __nv_bfloat16* __restrict__ l, int n8){
  int i = blockIdx.x*256 + threadIdx.x;
  if (i >= n8) return;
  float4 a = ((const float4*)s)[2*i], b = ((const float4*)s)[2*i+1];
  float v[8] = {a.x,a.y,a.z,a.w,b.x,b.y,b.z,b.w};
  __nv_bfloat162 H[4], L[4];
  #pragma unroll
  for (int j=0;j<4;j++){
    __nv_bfloat16 h0 = __float2bfloat16_rn(v[2*j]);
    __nv_bfloat16 h1 = __float2bfloat16_rn(v[2*j+1]);
    H[j] = __nv_bfloat162(h0, h1);
    L[j] = __nv_bfloat162(__float2bfloat16_rn(v[2*j]   - __bfloat162float(h0)),
                          __float2bfloat16_rn(v[2*j+1] - __bfloat162float(h1)));
  }
  ((uint4*)h)[i] = *(uint4*)H;
  ((uint4*)l)[i] = *(uint4*)L;
}

// =======================================================================
// HMMA GEMM: CTA tile 256(M) x 128(N), K = 3*512 (bf16 hi/lo 3-term split)
// grid = (32, 4, nz). Warp tile 64x64 (8 warps, 4Mx2N).
// =======================================================================
template<int MODE>
__global__ __launch_bounds__(256,1) void hgemm(
    const __nv_bfloat16* __restrict__ ah, const __nv_bfloat16* __restrict__ al,
    int lda, int windowed, int zW0,
    const float* __restrict__ bias0, const float* __restrict__ bias1, int bSplit,
    float* __restrict__ out, int ldo, long long oZ,
    const float* __restrict__ Q,
    const float* __restrict__ R,
    float* __restrict__ partial, int pZ0)
{
  const int z = blockIdx.z;
  const int widx = windowed ? (z + (z>=8 ? 1 : 0)) : 0;
  const __nv_bfloat16* Ah = ah + widx*Dd;
  const __nv_bfloat16* Al = al + widx*Dd;
  const __nv_bfloat16* Wh = g_wh + (size_t)(zW0+z)*WSZ;
  const __nv_bfloat16* Wl = g_wl + (size_t)(zW0+z)*WSZ;
  const float* bp = (z < bSplit) ? bias0 + (size_t)z*Dd : bias1 + (size_t)(z-bSplit)*Dd;
  float* outPtr = out ? out + (size_t)widx*Dd + (size_t)z*oZ : nullptr;

  const int tid = threadIdx.x, lane = tid & 31, wid = tid >> 5;
  const int warpM = wid >> 1, warpN = wid & 1;
  const int bBase = blockIdx.x * 256;
  const int nBase = blockIdx.y * 128;

  extern __shared__ char dsm[];
  const uint32_t dynU = (smem_u32(dsm) + 1023u) & ~1023u;
  __shared__ float biasS[128];
  __shared__ float redS[256][2];

  if (tid < 32) ((float4*)biasS)[tid] = ((const float4*)(bp + nBase))[tid];

  float acc[4][8][4];
  #pragma unroll
  for (int m=0;m<4;m++) for (int n=0;n<8;n++) for (int i=0;i<4;i++) acc[m][n][i]=0.f;

  // ldmatrix address precompute
  uint32_t aRowOff[4], bRowOff[4];
  #pragma unroll
  for (int i=0;i<4;i++){
    aRowOff[i] = (uint32_t)((warpM*64 + i*16 + (lane&15)) * 128);
    bRowOff[i] = (uint32_t)((warpN*64 + i*16 + (lane&7) + ((lane&16)>>1)) * 128);
  }
  const int aXb = lane >> 4, bXb = (lane >> 3) & 1, lx = lane & 7;

  auto loadStage = [&](int s, int buf){
    const int term = s >> 3, kOff = (s & 7) * 64;
    const __nv_bfloat16* As = (term == 2) ? Al : Ah;
    const __nv_bfloat16* Bs = (term == 1) ? Wl : Wh;
    uint32_t aB = dynU + buf*STG_BYTES, bB = aB + 32768;
    #pragma unroll
    for (int i=0;i<8;i++){
      int idx = i*256 + tid, row = idx>>3, g = idx&7;
      const void* gp = As + (size_t)(bBase+row)*(size_t)lda + kOff + g*8;
      CP16(aB + (uint32_t)(row*128 + ((g ^ (row&7))<<4)), gp);
    }
    #pragma unroll
    for (int i=0;i<4;i++){
      int idx = i*256 + tid, row = idx>>3, g = idx&7;
      const void* gp = Bs + (size_t)(nBase+row)*Dd + kOff + g*8;
      CP16(bB + (uint32_t)(row*128 + ((g ^ (row&7))<<4)), gp);
    }
  };

  loadStage(0,0); CPCOMMIT();
  loadStage(1,1); CPCOMMIT();
  loadStage(2,2); CPCOMMIT();

  int buf = 0;
  for (int s = 0; s < NSTG; s++){
    CPWAIT2();
    __syncthreads();
    const uint32_t aB = dynU + buf*STG_BYTES, bB = aB + 32768;
    #pragma unroll
    for (int q=0;q<4;q++){
      uint32_t aSel = (uint32_t)((((2*q + aXb) ^ lx)) << 4);
      uint32_t bSel = (uint32_t)((((2*q + bXb) ^ lx)) << 4);
      uint32_t afr[4][4], bfr[4][4];
      #pragma unroll
      for (int mt=0;mt<4;mt++) ldsm4(afr[mt], aB + aRowOff[mt] + aSel);
      #pragma unroll
      for (int nt2=0;nt2<4;nt2++) ldsm4(bfr[nt2], bB + bRowOff[nt2] + bSel);
      #pragma unroll
      for (int mt=0;mt<4;mt++)
        #pragma unroll
        for (int nt2=0;nt2<4;nt2++){
          MMA(acc[mt][nt2*2],   afr[mt], bfr[nt2][0], bfr[nt2][1]);
          MMA(acc[mt][nt2*2+1], afr[mt], bfr[nt2][2], bfr[nt2][3]);
        }
    }
    __syncthreads();
    if (s + 3 < NSTG) loadStage(s+3, buf);
    CPCOMMIT();                       // empty-group trick keeps wait_group 2 exact
    buf = (buf + 1 == 3) ? 0 : buf + 1;
  }

  // ---------------- epilogue ----------------
  if constexpr (MODE == M_STORE){
    #pragma unroll
    for (int mt=0;mt<4;mt++){
      const int rl0 = warpM*64 + mt*16 + (lane>>2);
      float* o0 = outPtr + (size_t)(bBase+rl0)*(size_t)ldo;
      float* o1 = o0 + (size_t)8*(size_t)ldo;
      #pragma unroll
      for (int nt=0;nt<8;nt++){
        const int bl = warpN*64 + nt*8 + ((lane&3)<<1);
        const int c  = nBase + bl;
        float bx = biasS[bl], by = biasS[bl+1];
        float2 v0 = { acc[mt][nt][0]+bx, acc[mt][nt][1]+by };
        float2 v1 = { acc[mt][nt][2]+bx, acc[mt][nt][3]+by };
        *(float2*)(o0 + c) = v0;
        *(float2*)(o1 + c) = v1;
      }
    }
  }
  else if constexpr (MODE == M_DOT){
    #pragma unroll
    for (int mt=0;mt<4;mt++){
      const int rl0 = warpM*64 + mt*16 + (lane>>2);
      const float* q0 = Q + (size_t)(bBase+rl0)*Dd;
      const float* q1 = q0 + (size_t)8*Dd;
      float s0 = 0.f, s1 = 0.f;
      #pragma unroll
      for (int nt=0;nt<8;nt++){
        const int bl = warpN*64 + nt*8 + ((lane&3)<<1);
        const int c  = nBase + bl;
        float bx = biasS[bl], by = biasS[bl+1];
        float2 qa = *(const float2*)(q0 + c);
        float2 qb = *(const float2*)(q1 + c);
        s0 += (acc[mt][nt][0]+bx)*qa.x + (acc[mt][nt][1]+by)*qa.y;
        s1 += (acc[mt][nt][2]+bx)*qb.x + (acc[mt][nt][3]+by)*qb.y;
      }
      s0 += __shfl_xor_sync(0xffffffffu, s0, 1); s0 += __shfl_xor_sync(0xffffffffu, s0, 2);
      s1 += __shfl_xor_sync(0xffffffffu, s1, 1); s1 += __shfl_xor_sync(0xffffffffu, s1, 2);
      if ((lane&3) == 0){ redS[rl0][warpN] = s0; redS[rl0+8][warpN] = s1; }
    }
    __syncthreads();
    {
      float p = redS[tid][0] + redS[tid][1];
      partial[((size_t)z*Bsz + bBase + tid)*4 + blockIdx.y] = p;
    }
  }
  else { // M_NORM / M_NORM_RES
    #pragma unroll
    for (int mt=0;mt<4;mt++){
      const int rl0 = warpM*64 + mt*16 + (lane>>2);
      float* o0 = outPtr + (size_t)(bBase+rl0)*(size_t)ldo;
      float* o1 = o0 + (size_t)8*(size_t)ldo;
      const float* r0p = (MODE==M_NORM_RES) ? (R + (size_t)(bBase+rl0)*XS) : nullptr;
      const float* r1p = (MODE==M_NORM_RES) ? (r0p + (size_t)8*XS) : nullptr;
      float s0 = 0.f, s1 = 0.f;
      #pragma unroll
      for (int nt=0;nt<8;nt++){
        const int bl = warpN*64 + nt*8 + ((lane&3)<<1);
        const int c  = nBase + bl;
        float bx = biasS[bl], by = biasS[bl+1];
        float v00 = acc[mt][nt][0]+bx, v01 = acc[mt][nt][1]+by;
        float v10 = acc[mt][nt][2]+bx, v11 = acc[mt][nt][3]+by;
        if constexpr (MODE==M_NORM_RES){
          float2 ra = *(const float2*)(r0p + c);
          float2 rb = *(const float2*)(r1p + c);
          v00 += ra.x; v01 += ra.y; v10 += rb.x; v11 += rb.y;
        }
        *(float2*)(o0 + c) = make_float2(v00, v01);
        *(float2*)(o1 + c) = make_float2(v10, v11);
        s0 += v00*v00 + v01*v01;
        s1 += v10*v10 + v11*v11;
      }
      s0 += __shfl_xor_sync(0xffffffffu, s0, 1); s0 += __shfl_xor_sync(0xffffffffu, s0, 2);
      s1 += __shfl_xor_sync(0xffffffffu, s1, 1); s1 += __shfl_xor_sync(0xffffffffu, s1, 2);
      if ((lane&3) == 0){ redS[rl0][warpN] = s0; redS[rl0+8][warpN] = s1; }
    }
    __syncthreads();
    {
      float p = redS[tid][0] + redS[tid][1];
      partial[((size_t)(pZ0+z)*Bsz + bBase + tid)*4 + blockIdx.y] = p;
    }
  }
}

// =======================================================================
// second pass: per-row l2 normalization in-place on out, 17 segments
// =======================================================================
__global__ void norm_scale(float* __restrict__ out, const float* __restrict__ partial){
  const int b = blockIdx.x, zi = blockIdx.y, t = threadIdx.x;
  const float* p = partial + ((size_t)zi*Bsz + b)*4;
  float ss = p[0]+p[1]+p[2]+p[3];
  float sc = 1.f / fmaxf(sqrtf(ss), 1e-12f);
  int col0 = (zi==16) ? 4096 : ((zi<8) ? zi*512 : (zi+1)*512);
  float4* row = (float4*)(out + (size_t)b*XS + col0);
  float4 v = row[t];
  v.x*=sc; v.y*=sc; v.z*=sc; v.w*=sc;
  row[t] = v;
}

// =======================================================================
// mix: attn = q.kc; v = l2norm(xc*attn + sum_w ap*xp_w + sum_w an*xn_w)
// ap/an assembled from dot partials (4 per (b,z)).
// =======================================================================
__global__ void mix_kernel(const float* __restrict__ x, float* __restrict__ outv,
                           const float* __restrict__ q, const float* __restrict__ kc,
                           const float* __restrict__ dotP)
{
  __shared__ float sb[4];
  const int b = blockIdx.x, t = threadIdx.x;
  const float4* xr = (const float4*)(x + (size_t)b*XS);

  float4 q4 = ((const float4*)(q  + (size_t)b*Dd))[t];
  float4 k4 = ((const float4*)(kc + (size_t)b*Dd))[t];
  float part = q4.x*k4.x + q4.y*k4.y + q4.z*k4.z + q4.w*k4.w;
  #pragma unroll
  for (int o=16;o;o>>=1) part += __shfl_xor_sync(0xffffffffu, part, o);
  if ((t & 31) == 0) sb[t>>5] = part;
  __syncthreads();
  const float attn = sb[0] + sb[1] + sb[2] + sb[3];
  __syncthreads();

  float4 xc4 = xr[1024 + t];
  float4 acc;
  acc.x = xc4.x*attn; acc.y = xc4.y*attn; acc.z = xc4.z*attn; acc.w = xc4.w*attn;
  #pragma unroll
  for (int w=0;w<8;w++){
    float4 pa = *(const float4*)(dotP + ((size_t)w*Bsz + b)*4);
    float aw = pa.x + pa.y + pa.z + pa.w;
    float4 p4 = xr[w*128 + t];
    acc.x += aw*p4.x; acc.y += aw*p4.y; acc.z += aw*p4.z; acc.w += aw*p4.w;
    float4 pn = *(const float4*)(dotP + ((size_t)(8+w)*Bsz + b)*4);
    float nw = pn.x + pn.y + pn.z + pn.w;
    float4 n4 = xr[(9+w)*128 + t];
    acc.x += nw*n4.x; acc.y += nw*n4.y; acc.z += nw*n4.z; acc.w += nw*n4.w;
  }
  float ss = acc.x*acc.x + acc.y*acc.y + acc.z*acc.z + acc.w*acc.w;
  #pragma unroll
  for (int o=16;o;o>>=1) ss += __shfl_xor_sync(0xffffffffu, ss, o);
  if ((t & 31) == 0) sb[t>>5] = ss;
  __syncthreads();
  float tot = sb[0] + sb[1] + sb[2] + sb[3];
  float sc = 1.f / fmaxf(sqrtf(tot), 1e-12f);
  float4 v; v.x = acc.x*sc; v.y = acc.y*sc; v.z = acc.z*sc; v.w = acc.w*sc;
  ((float4*)(outv + (size_t)b*Dd))[t] = v;
}

// =======================================================================
extern "C" void kernel_launch(void* const* d_in, const int* in_sizes, int n_in,
                              void* d_out, int out_size)
{
  const float* x   = (const float*)d_in[0];
  const float* Wq  = (const float*)d_in[1];
  const float* bq  = (const float*)d_in[2];
  const float* Wkc = (const float*)d_in[3];
  const float* bkc = (const float*)d_in[4];
  const float* Wkp = (const float*)d_in[5];
  const float* bkp = (const float*)d_in[6];
  const float* Wkn = (const float*)d_in[7];
  const float* bkn = (const float*)d_in[8];
  const float* Wfp = (const float*)d_in[9];
  const float* bfp = (const float*)d_in[10];
  const float* Wfn = (const float*)d_in[11];
  const float* bfn = (const float*)d_in[12];
  const float* Wfc = (const float*)d_in[13];
  const float* bfc = (const float*)d_in[14];
  float* out = (float*)d_out;

  __nv_bfloat16 *xh, *xl, *vh, *vl, *wh, *wl;
  float *qkc, *v, *dotP, *nrmP;
  cudaGetSymbolAddress((void**)&xh, g_xh);
  cudaGetSymbolAddress((void**)&xl, g_xl);
  cudaGetSymbolAddress((void**)&wh, g_wh);
  cudaGetSymbolAddress((void**)&wl, g_wl);
  cudaGetSymbolAddress((void**)&vh, g_vh);
  cudaGetSymbolAddress((void**)&vl, g_vl);
  cudaGetSymbolAddress((void**)&qkc,  s_qkc);
  cudaGetSymbolAddress((void**)&v,    s_v);
  cudaGetSymbolAddress((void**)&dotP, s_dotP);
  cudaGetSymbolAddress((void**)&nrmP, s_nrmP);
  float* q  = qkc;
  float* kc = qkc + (size_t)Bsz*Dd;

  cudaFuncSetAttribute(hgemm<M_STORE>,    cudaFuncAttributeMaxDynamicSharedMemorySize, DYN_SMEM);
  cudaFuncSetAttribute(hgemm<M_DOT>,      cudaFuncAttributeMaxDynamicSharedMemorySize, DYN_SMEM);
  cudaFuncSetAttribute(hgemm<M_NORM>,     cudaFuncAttributeMaxDynamicSharedMemorySize, DYN_SMEM);
  cudaFuncSetAttribute(hgemm<M_NORM_RES>, cudaFuncAttributeMaxDynamicSharedMemorySize, DYN_SMEM);

  // ---- fp32 -> bf16 hi/lo ----
  { int n8 = (Bsz*XS)/8; cvt8<<<(n8+255)/256, 256>>>(x, xh, xl, n8); }
  { int n8 = WSZ/8;      cvt8<<<(n8+255)/256, 256>>>(Wq,  wh,                  wl,                  n8); }
  { int n8 = WSZ/8;      cvt8<<<(n8+255)/256, 256>>>(Wkc, wh + WSZ,            wl + WSZ,            n8); }
  { int n8 = 8*WSZ/8;    cvt8<<<(n8+255)/256, 256>>>(Wkp, wh + 2*(size_t)WSZ,  wl + 2*(size_t)WSZ,  n8); }
  { int n8 = 8*WSZ/8;    cvt8<<<(n8+255)/256, 256>>>(Wkn, wh + 10*(size_t)WSZ, wl + 10*(size_t)WSZ, n8); }
  { int n8 = 8*WSZ/8;    cvt8<<<(n8+255)/256, 256>>>(Wfp, wh + 18*(size_t)WSZ, wl + 18*(size_t)WSZ, n8); }
  { int n8 = 8*WSZ/8;    cvt8<<<(n8+255)/256, 256>>>(Wfn, wh + 26*(size_t)WSZ, wl + 26*(size_t)WSZ, n8); }
  { int n8 = WSZ/8;      cvt8<<<(n8+255)/256, 256>>>(Wfc, wh + 34*(size_t)WSZ, wl + 34*(size_t)WSZ, n8); }

  // ---- q / kc ----
  hgemm<M_STORE><<<dim3(32,4,2), 256, DYN_SMEM>>>(
      xh+4096, xl+4096, XS, 0, 0, bq, bkc, 1,
      qkc, Dd, (long long)Bsz*Dd, nullptr, nullptr, nullptr, 0);

  // ---- ap/an partial dots (kp/kn never materialized) ----
  hgemm<M_DOT><<<dim3(32,4,16), 256, DYN_SMEM>>>(
      xh, xl, XS, 1, 2, bkp, bkn, 8,
      nullptr, 0, 0, q, nullptr, dotP, 0);

  // ---- fp/fn raw + sumsq partials, straight into d_out ----
  hgemm<M_NORM><<<dim3(32,4,16), 256, DYN_SMEM>>>(
      xh, xl, XS, 1, 18, bfp, bfn, 8,
      out, XS, 0, nullptr, nullptr, nrmP, 0);

  // ---- mix -> v ; convert v ----
  mix_kernel<<<Bsz, 128>>>(x, v, q, kc, dotP);
  { int n8 = (Bsz*Dd)/8; cvt8<<<(n8+255)/256, 256>>>(v, vh, vl, n8); }

  // ---- fc (+ residual xc) raw + partials ----
  hgemm<M_NORM_RES><<<dim3(32,4,1), 256, DYN_SMEM>>>(
      vh, vl, Dd, 0, 34, bfc, bfc, 1,
      out+4096, XS, 0, nullptr, x+4096, nrmP, 16);

  // ---- in-place l2 normalization of all 17 segments ----
  norm_scale<<<dim3(Bsz,17), 128>>>(out, nrmP);
}

// round 4
// speedup vs baseline: 3.6425x; 1.0987x over previous
#include <cuda_runtime.h>
#include <cuda_bf16.h>
#include <cstdint>

#define Bsz 8192
#define Dd  512
#define XS  8704           // 17*512 row stride of x / out
#define WSZ 262144         // 512*512 per weight matrix
#define NW  35
#define NMAC 8             // 8 macro k-chunks of 64 (all 3 terms per chunk)
#define BUF_BYTES 98304    // Ah 32K + Al 32K + Bh 16K + Bl 16K
#define DYN_SMEM (2*BUF_BYTES + 1024)

enum { M_STORE=0, M_DOT=1, M_NORM=2, M_NORM_RES=3 };

// ---------------- device scratch (allocation-free rule) ----------------
__device__ __align__(256) __nv_bfloat16 g_xh[Bsz*XS];
__device__ __align__(256) __nv_bfloat16 g_xl[Bsz*XS];
__device__ __align__(256) __nv_bfloat16 g_wh[NW*WSZ];
__device__ __align__(256) __nv_bfloat16 g_wl[NW*WSZ];
__device__ __align__(256) __nv_bfloat16 g_vh[Bsz*Dd];
__device__ __align__(256) __nv_bfloat16 g_vl[Bsz*Dd];
__device__ __align__(256) float s_qkc[2*Bsz*Dd];     // q then kc
__device__ __align__(256) float s_v[Bsz*Dd];
__device__ __align__(256) float s_dotP[16*Bsz*4];    // [z][b][ctaN]
__device__ __align__(256) float s_nrmP[17*Bsz*4];    // [zi][b][ctaN]

// ---------------- ptx helpers ----------------
__device__ __forceinline__ uint32_t smem_u32(const void* p){
  uint32_t a;
  asm("{ .reg .u64 t; cvta.to.shared.u64 t, %1; cvt.u32.u64 %0, t; }" : "=r"(a) : "l"(p));
  return a;
}
#define CP16(s,g) asm volatile("cp.async.cg.shared.global [%0], [%1], 16;" :: "r"(s), "l"(g))
#define CPCOMMIT() asm volatile("cp.async.commit_group;" ::: "memory")
#define CPWAIT0()  asm volatile("cp.async.wait_group 0;" ::: "memory")

__device__ __forceinline__ void ldsm4(uint32_t* r, uint32_t a){
  asm volatile("ldmatrix.sync.aligned.m8n8.x4.shared.b16 {%0,%1,%2,%3}, [%4];"
    : "=r"(r[0]),"=r"(r[1]),"=r"(r[2]),"=r"(r[3]) : "r"(a));
}
#define MMA(c,a,b0,b1) \
  asm volatile("mma.sync.aligned.m16n8k16.row.col.f32.bf16.bf16.f32 " \
    "{%0,%1,%2,%3},{%4,%5,%6,%7},{%8,%9},{%0,%1,%2,%3};" \
    : "+f"((c)[0]),"+f"((c)[1]),"+f"((c)[2]),"+f"((c)[3]) \
    : "r"((a)[0]),"r"((a)[1]),"r"((a)[2]),"r"((a)[3]),"r"(b0),"r"(b1))

// ---------------- fp32 -> bf16 hi/lo split ----------------
__global__ void cvt8(const float* __restrict__ s, __nv_bfloat16* __restrict__ h,
                     __nv_bfloat16* __restrict__ l, int n8){
  int i = blockIdx.x*256 + threadIdx.x;
  if (i >= n8) return;
  float4 a = ((const float4*)s)[2*i], b = ((const float4*)s)[2*i+1];
  float v[8] = {a.x,a.y,a.z,a.w,b.x,b.y,b.z,b.w};
  __nv_bfloat162 H[4], L[4];
  #pragma unroll
  for (int j=0;j<4;j++){
    __nv_bfloat16 h0 = __float2bfloat16_rn(v[2*j]);
    __nv_bfloat16 h1 = __float2bfloat16_rn(v[2*j+1]);
    H[j] = __nv_bfloat162(h0, h1);
    L[j] = __nv_bfloat162(__float2bfloat16_rn(v[2*j]   - __bfloat162float(h0)),
                          __float2bfloat16_rn(v[2*j+1] - __bfloat162float(h1)));
  }
  ((uint4*)h)[i] = *(uint4*)H;
  ((uint4*)l)[i] = *(uint4*)L;
}

// =======================================================================
// HMMA GEMM: CTA tile 256(M) x 128(N), 3-term bf16 split, macro k-chunks:
// per chunk load Ah/Al/Bh/Bl once, issue AhBh + AhBl + AlBh from same smem.
// grid = (32, 4, nz). Warp tile 64x64 (8 warps, 4Mx2N).
// =======================================================================
template<int MODE>
__global__ __launch_bounds__(256,1) void hgemm(
    const __nv_bfloat16* __restrict__ ah, const __nv_bfloat16* __restrict__ al,
    int lda, int windowed, int zW0,
    const float* __restrict__ bias0, const float* __restrict__ bias1, int bSplit,
    float* __restrict__ out, int ldo, long long oZ,
    const float* __restrict__ Q,
    const float* __restrict__ R,
    float* __restrict__ partial, int pZ0)
{
  const int z = blockIdx.z;
  const int widx = windowed ? (z + (z>=8 ? 1 : 0)) : 0;
  const __nv_bfloat16* Ah = ah + widx*Dd;
  const __nv_bfloat16* Al = al + widx*Dd;
  const __nv_bfloat16* Wh = g_wh + (size_t)(zW0+z)*WSZ;
  const __nv_bfloat16* Wl = g_wl + (size_t)(zW0+z)*WSZ;
  const float* bp = (z < bSplit) ? bias0 + (size_t)z*Dd : bias1 + (size_t)(z-bSplit)*Dd;
  float* outPtr = out ? out + (size_t)widx*Dd + (size_t)z*oZ : nullptr;

  const int tid = threadIdx.x, lane = tid & 31, wid = tid >> 5;
  const int warpM = wid >> 1, warpN = wid & 1;
  const int bBase = blockIdx.x * 256;
  const int nBase = blockIdx.y * 128;

  extern __shared__ char dsm[];
  const uint32_t dynU = (smem_u32(dsm) + 1023u) & ~1023u;
  __shared__ float biasS[128];
  __shared__ float redS[256][2];

  if (tid < 32) ((float4*)biasS)[tid] = ((const float4*)(bp + nBase))[tid];

  float acc[4][8][4];
  #pragma unroll
  for (int m=0;m<4;m++) for (int n=0;n<8;n++) for (int i=0;i<4;i++) acc[m][n][i]=0.f;

  // ldmatrix address precompute (byte offsets within a tile)
  uint32_t aRowOff[4], bRowOff[4];
  #pragma unroll
  for (int i=0;i<4;i++){
    aRowOff[i] = (uint32_t)((warpM*64 + i*16 + (lane&15)) * 128);
    bRowOff[i] = (uint32_t)((warpN*64 + i*16 + (lane&7) + ((lane&16)>>1)) * 128);
  }
  const int aXb = lane >> 4, bXb = (lane >> 3) & 1, lx = lane & 7;

  // macro-stage load: Ah/Al (256x64 each) + Bh/Bl (128x64 each), one k-chunk
  auto loadStage = [&](int kc, int buf){
    const int kOff = kc * 64;
    const uint32_t base = dynU + buf*BUF_BYTES;
    #pragma unroll
    for (int i=0;i<8;i++){
      int idx = i*256 + tid, row = idx>>3, g = idx&7;
      uint32_t sw = (uint32_t)(row*128 + ((g ^ (row&7))<<4));
      size_t go = (size_t)(bBase+row)*(size_t)lda + kOff + g*8;
      CP16(base + sw,         Ah + go);
      CP16(base + 32768 + sw, Al + go);
    }
    #pragma unroll
    for (int i=0;i<4;i++){
      int idx = i*256 + tid, row = idx>>3, g = idx&7;
      uint32_t sw = (uint32_t)(row*128 + ((g ^ (row&7))<<4));
      size_t go = (size_t)(nBase+row)*Dd + kOff + g*8;
      CP16(base + 65536 + sw, Wh + go);
      CP16(base + 81920 + sw, Wl + go);
    }
  };

  loadStage(0, 0); CPCOMMIT();

  int buf = 0;
  for (int s = 0; s < NMAC; s++){
    CPWAIT0();
    __syncthreads();
    if (s + 1 < NMAC){ loadStage(s+1, buf^1); CPCOMMIT(); }
    const uint32_t aHB = dynU + buf*BUF_BYTES;
    const uint32_t aLB = aHB + 32768;
    const uint32_t bHB = aHB + 65536;
    const uint32_t bLB = aHB + 81920;
    #pragma unroll
    for (int q=0;q<4;q++){
      const uint32_t aSel = (uint32_t)((((2*q + aXb) ^ lx)) << 4);
      const uint32_t bSel = (uint32_t)((((2*q + bXb) ^ lx)) << 4);
      uint32_t aF[4][4], bH[4][4], bL[4][4];
      #pragma unroll
      for (int mt=0;mt<4;mt++) ldsm4(aF[mt], aHB + aRowOff[mt] + aSel);
      #pragma unroll
      for (int nt=0;nt<4;nt++) ldsm4(bH[nt], bHB + bRowOff[nt] + bSel);
      // Ah * Bh
      #pragma unroll
      for (int mt=0;mt<4;mt++)
        #pragma unroll
        for (int nt=0;nt<4;nt++){
          MMA(acc[mt][nt*2],   aF[mt], bH[nt][0], bH[nt][1]);
          MMA(acc[mt][nt*2+1], aF[mt], bH[nt][2], bH[nt][3]);
        }
      #pragma unroll
      for (int nt=0;nt<4;nt++) ldsm4(bL[nt], bLB + bRowOff[nt] + bSel);
      // Ah * Bl
      #pragma unroll
      for (int mt=0;mt<4;mt++)
        #pragma unroll
        for (int nt=0;nt<4;nt++){
          MMA(acc[mt][nt*2],   aF[mt], bL[nt][0], bL[nt][1]);
          MMA(acc[mt][nt*2+1], aF[mt], bL[nt][2], bL[nt][3]);
        }
      #pragma unroll
      for (int mt=0;mt<4;mt++) ldsm4(aF[mt], aLB + aRowOff[mt] + aSel);
      // Al * Bh
      #pragma unroll
      for (int mt=0;mt<4;mt++)
        #pragma unroll
        for (int nt=0;nt<4;nt++){
          MMA(acc[mt][nt*2],   aF[mt], bH[nt][0], bH[nt][1]);
          MMA(acc[mt][nt*2+1], aF[mt], bH[nt][2], bH[nt][3]);
        }
    }
    buf ^= 1;
  }

  // ---------------- epilogue ----------------
  if constexpr (MODE == M_STORE){
    #pragma unroll
    for (int mt=0;mt<4;mt++){
      const int rl0 = warpM*64 + mt*16 + (lane>>2);
      float* o0 = outPtr + (size_t)(bBase+rl0)*(size_t)ldo;
      float* o1 = o0 + (size_t)8*(size_t)ldo;
      #pragma unroll
      for (int nt=0;nt<8;nt++){
        const int bl = warpN*64 + nt*8 + ((lane&3)<<1);
        const int c  = nBase + bl;
        float bx = biasS[bl], by = biasS[bl+1];
        float2 v0 = { acc[mt][nt][0]+bx, acc[mt][nt][1]+by };
        float2 v1 = { acc[mt][nt][2]+bx, acc[mt][nt][3]+by };
        *(float2*)(o0 + c) = v0;
        *(float2*)(o1 + c) = v1;
      }
    }
  }
  else if constexpr (MODE == M_DOT){
    #pragma unroll
    for (int mt=0;mt<4;mt++){
      const int rl0 = warpM*64 + mt*16 + (lane>>2);
      const float* q0 = Q + (size_t)(bBase+rl0)*Dd;
      const float* q1 = q0 + (size_t)8*Dd;
      float s0 = 0.f, s1 = 0.f;
      #pragma unroll
      for (int nt=0;nt<8;nt++){
        const int bl = warpN*64 + nt*8 + ((lane&3)<<1);
        const int c  = nBase + bl;
        float bx = biasS[bl], by = biasS[bl+1];
        float2 qa = *(const float2*)(q0 + c);
        float2 qb = *(const float2*)(q1 + c);
        s0 += (acc[mt][nt][0]+bx)*qa.x + (acc[mt][nt][1]+by)*qa.y;
        s1 += (acc[mt][nt][2]+bx)*qb.x + (acc[mt][nt][3]+by)*qb.y;
      }
      s0 += __shfl_xor_sync(0xffffffffu, s0, 1); s0 += __shfl_xor_sync(0xffffffffu, s0, 2);
      s1 += __shfl_xor_sync(0xffffffffu, s1, 1); s1 += __shfl_xor_sync(0xffffffffu, s1, 2);
      if ((lane&3) == 0){ redS[rl0][warpN] = s0; redS[rl0+8][warpN] = s1; }
    }
    __syncthreads();
    {
      float p = redS[tid][0] + redS[tid][1];
      partial[((size_t)z*Bsz + bBase + tid)*4 + blockIdx.y] = p;
    }
  }
  else { // M_NORM / M_NORM_RES
    #pragma unroll
    for (int mt=0;mt<4;mt++){
      const int rl0 = warpM*64 + mt*16 + (lane>>2);
      float* o0 = outPtr + (size_t)(bBase+rl0)*(size_t)ldo;
      float* o1 = o0 + (size_t)8*(size_t)ldo;
      const float* r0p = (MODE==M_NORM_RES) ? (R + (size_t)(bBase+rl0)*XS) : nullptr;
      const float* r1p = (MODE==M_NORM_RES) ? (r0p + (size_t)8*XS) : nullptr;
      float s0 = 0.f, s1 = 0.f;
      #pragma unroll
      for (int nt=0;nt<8;nt++){
        const int bl = warpN*64 + nt*8 + ((lane&3)<<1);
        const int c  = nBase + bl;
        float bx = biasS[bl], by = biasS[bl+1];
        float v00 = acc[mt][nt][0]+bx, v01 = acc[mt][nt][1]+by;
        float v10 = acc[mt][nt][2]+bx, v11 = acc[mt][nt][3]+by;
        if constexpr (MODE==M_NORM_RES){
          float2 ra = *(const float2*)(r0p + c);
          float2 rb = *(const float2*)(r1p + c);
          v00 += ra.x; v01 += ra.y; v10 += rb.x; v11 += rb.y;
        }
        *(float2*)(o0 + c) = make_float2(v00, v01);
        *(float2*)(o1 + c) = make_float2(v10, v11);
        s0 += v00*v00 + v01*v01;
        s1 += v10*v10 + v11*v11;
      }
      s0 += __shfl_xor_sync(0xffffffffu, s0, 1); s0 += __shfl_xor_sync(0xffffffffu, s0, 2);
      s1 += __shfl_xor_sync(0xffffffffu, s1, 1); s1 += __shfl_xor_sync(0xffffffffu, s1, 2);
      if ((lane&3) == 0){ redS[rl0][warpN] = s0; redS[rl0+8][warpN] = s1; }
    }
    __syncthreads();
    {
      float p = redS[tid][0] + redS[tid][1];
      partial[((size_t)(pZ0+z)*Bsz + bBase + tid)*4 + blockIdx.y] = p;
    }
  }
}

// =======================================================================
// second pass: per-row l2 normalization in-place on out, 17 segments
// =======================================================================
__global__ void norm_scale(float* __restrict__ out, const float* __restrict__ partial){
  const int b = blockIdx.x, zi = blockIdx.y, t = threadIdx.x;
  const float* p = partial + ((size_t)zi*Bsz + b)*4;
  float ss = p[0]+p[1]+p[2]+p[3];
  float sc = 1.f / fmaxf(sqrtf(ss), 1e-12f);
  int col0 = (zi==16) ? 4096 : ((zi<8) ? zi*512 : (zi+1)*512);
  float4* row = (float4*)(out + (size_t)b*XS + col0);
  float4 v = row[t];
  v.x*=sc; v.y*=sc; v.z*=sc; v.w*=sc;
  row[t] = v;
}

// =======================================================================
// mix: attn = q.kc; v = l2norm(xc*attn + sum_w ap*xp_w + sum_w an*xn_w)
// =======================================================================
__global__ void mix_kernel(const float* __restrict__ x, float* __restrict__ outv,
                           const float* __restrict__ q, const float* __restrict__ kc,
                           const float* __restrict__ dotP)
{
  __shared__ float sb[4];
  const int b = blockIdx.x, t = threadIdx.x;
  const float4* xr = (const float4*)(x + (size_t)b*XS);

  float4 q4 = ((const float4*)(q  + (size_t)b*Dd))[t];
  float4 k4 = ((const float4*)(kc + (size_t)b*Dd))[t];
  float part = q4.x*k4.x + q4.y*k4.y + q4.z*k4.z + q4.w*k4.w;
  #pragma unroll
  for (int o=16;o;o>>=1) part += __shfl_xor_sync(0xffffffffu, part, o);
  if ((t & 31) == 0) sb[t>>5] = part;
  __syncthreads();
  const float attn = sb[0] + sb[1] + sb[2] + sb[3];
  __syncthreads();

  float4 xc4 = xr[1024 + t];
  float4 acc;
  acc.x = xc4.x*attn; acc.y = xc4.y*attn; acc.z = xc4.z*attn; acc.w = xc4.w*attn;
  #pragma unroll
  for (int w=0;w<8;w++){
    float4 pa = *(const float4*)(dotP + ((size_t)w*Bsz + b)*4);
    float aw = pa.x + pa.y + pa.z + pa.w;
    float4 p4 = xr[w*128 + t];
    acc.x += aw*p4.x; acc.y += aw*p4.y; acc.z += aw*p4.z; acc.w += aw*p4.w;
    float4 pn = *(const float4*)(dotP + ((size_t)(8+w)*Bsz + b)*4);
    float nw = pn.x + pn.y + pn.z + pn.w;
    float4 n4 = xr[(9+w)*128 + t];
    acc.x += nw*n4.x; acc.y += nw*n4.y; acc.z += nw*n4.z; acc.w += nw*n4.w;
  }
  float ss = acc.x*acc.x + acc.y*acc.y + acc.z*acc.z + acc.w*acc.w;
  #pragma unroll
  for (int o=16;o;o>>=1) ss += __shfl_xor_sync(0xffffffffu, ss, o);
  if ((t & 31) == 0) sb[t>>5] = ss;
  __syncthreads();
  float tot = sb[0] + sb[1] + sb[2] + sb[3];
  float sc = 1.f / fmaxf(sqrtf(tot), 1e-12f);
  float4 v; v.x = acc.x*sc; v.y = acc.y*sc; v.z = acc.z*sc; v.w = acc.w*sc;
  ((float4*)(outv + (size_t)b*Dd))[t] = v;
}

// =======================================================================
extern "C" void kernel_launch(void* const* d_in, const int* in_sizes, int n_in,
                              void* d_out, int out_size)
{
  const float* x   = (const float*)d_in[0];
  const float* Wq  = (const float*)d_in[1];
  const float* bq  = (const float*)d_in[2];
  const float* Wkc = (const float*)d_in[3];
  const float* bkc = (const float*)d_in[4];
  const float* Wkp = (const float*)d_in[5];
  const float* bkp = (const float*)d_in[6];
  const float* Wkn = (const float*)d_in[7];
  const float* bkn = (const float*)d_in[8];
  const float* Wfp = (const float*)d_in[9];
  const float* bfp = (const float*)d_in[10];
  const float* Wfn = (const float*)d_in[11];
  const float* bfn = (const float*)d_in[12];
  const float* Wfc = (const float*)d_in[13];
  const float* bfc = (const float*)d_in[14];
  float* out = (float*)d_out;

  __nv_bfloat16 *xh, *xl, *vh, *vl, *wh, *wl;
  float *qkc, *v, *dotP, *nrmP;
  cudaGetSymbolAddress((void**)&xh, g_xh);
  cudaGetSymbolAddress((void**)&xl, g_xl);
  cudaGetSymbolAddress((void**)&wh, g_wh);
  cudaGetSymbolAddress((void**)&wl, g_wl);
  cudaGetSymbolAddress((void**)&vh, g_vh);
  cudaGetSymbolAddress((void**)&vl, g_vl);
  cudaGetSymbolAddress((void**)&qkc,  s_qkc);
  cudaGetSymbolAddress((void**)&v,    s_v);
  cudaGetSymbolAddress((void**)&dotP, s_dotP);
  cudaGetSymbolAddress((void**)&nrmP, s_nrmP);
  float* q  = qkc;
  float* kc = qkc + (size_t)Bsz*Dd;

  cudaFuncSetAttribute(hgemm<M_STORE>,    cudaFuncAttributeMaxDynamicSharedMemorySize, DYN_SMEM);
  cudaFuncSetAttribute(hgemm<M_DOT>,      cudaFuncAttributeMaxDynamicSharedMemorySize, DYN_SMEM);
  cudaFuncSetAttribute(hgemm<M_NORM>,     cudaFuncAttributeMaxDynamicSharedMemorySize, DYN_SMEM);
  cudaFuncSetAttribute(hgemm<M_NORM_RES>, cudaFuncAttributeMaxDynamicSharedMemorySize, DYN_SMEM);

  // ---- fp32 -> bf16 hi/lo ----
  { int n8 = (Bsz*XS)/8; cvt8<<<(n8+255)/256, 256>>>(x, xh, xl, n8); }
  { int n8 = WSZ/8;      cvt8<<<(n8+255)/256, 256>>>(Wq,  wh,                  wl,                  n8); }
  { int n8 = WSZ/8;      cvt8<<<(n8+255)/256, 256>>>(Wkc, wh + WSZ,            wl + WSZ,            n8); }
  { int n8 = 8*WSZ/8;    cvt8<<<(n8+255)/256, 256>>>(Wkp, wh + 2*(size_t)WSZ,  wl + 2*(size_t)WSZ,  n8); }
  { int n8 = 8*WSZ/8;    cvt8<<<(n8+255)/256, 256>>>(Wkn, wh + 10*(size_t)WSZ, wl + 10*(size_t)WSZ, n8); }
  { int n8 = 8*WSZ/8;    cvt8<<<(n8+255)/256, 256>>>(Wfp, wh + 18*(size_t)WSZ, wl + 18*(size_t)WSZ, n8); }
  { int n8 = 8*WSZ/8;    cvt8<<<(n8+255)/256, 256>>>(Wfn, wh + 26*(size_t)WSZ, wl + 26*(size_t)WSZ, n8); }
  { int n8 = WSZ/8;      cvt8<<<(n8+255)/256, 256>>>(Wfc, wh + 34*(size_t)WSZ, wl + 34*(size_t)WSZ, n8); }

  // ---- q / kc ----
  hgemm<M_STORE><<<dim3(32,4,2), 256, DYN_SMEM>>>(
      xh+4096, xl+4096, XS, 0, 0, bq, bkc, 1,
      qkc, Dd, (long long)Bsz*Dd, nullptr, nullptr, nullptr, 0);

  // ---- ap/an partial dots (kp/kn never materialized) ----
  hgemm<M_DOT><<<dim3(32,4,16), 256, DYN_SMEM>>>(
      xh, xl, XS, 1, 2, bkp, bkn, 8,
      nullptr, 0, 0, q, nullptr, dotP, 0);

  // ---- fp/fn raw + sumsq partials, straight into d_out ----
  hgemm<M_NORM><<<dim3(32,4,16), 256, DYN_SMEM>>>(
      xh, xl, XS, 1, 18, bfp, bfn, 8,
      out, XS, 0, nullptr, nullptr, nrmP, 0);

  // ---- mix -> v ; convert v ----
  mix_kernel<<<Bsz, 128>>>(x, v, q, kc, dotP);
  { int n8 = (Bsz*Dd)/8; cvt8<<<(n8+255)/256, 256>>>(v, vh, vl, n8); }

  // ---- fc (+ residual xc) raw + partials ----
  hgemm<M_NORM_RES><<<dim3(32,4,1), 256, DYN_SMEM>>>(
      vh, vl, Dd, 0, 34, bfc, bfc, 1,
      out+4096, XS, 0, nullptr, x+4096, nrmP, 16);

  // ---- in-place l2 normalization of all 17 segments ----
  norm_scale<<<dim3(Bsz,17), 128>>>(out, nrmP);
}

// round 5
// speedup vs baseline: 3.7487x; 1.0291x over previous
#include <cuda_runtime.h>
#include <cuda_bf16.h>
#include <cstdint>

#define Bsz 8192
#define Dd  512
#define XS  8704           // 17*512 row stride of x / out
#define WSZ 262144         // 512*512 per weight matrix
#define NW  35
#define NST 16             // 16 macro k-chunks of 32 (3 split terms per chunk)
#define STG 32768          // per-stage smem: A 16KB (hi|lo packed) + B 16KB
#define DYN_SMEM (3*STG + 1024)

enum { M_STORE=0, M_DOT=1, M_NORM=2, M_NORM_RES=3 };

// ---------------- device scratch (allocation-free rule) ----------------
__device__ __align__(256) __nv_bfloat16 g_xh[Bsz*XS];
__device__ __align__(256) __nv_bfloat16 g_xl[Bsz*XS];
__device__ __align__(256) __nv_bfloat16 g_wh[NW*WSZ];
__device__ __align__(256) __nv_bfloat16 g_wl[NW*WSZ];
__device__ __align__(256) __nv_bfloat16 g_vh[Bsz*Dd];
__device__ __align__(256) __nv_bfloat16 g_vl[Bsz*Dd];
__device__ __align__(256) float s_qkc[2*Bsz*Dd];     // q then kc
__device__ __align__(256) float s_v[Bsz*Dd];
__device__ __align__(256) float s_dotP[16*Bsz*4];    // [z][b][ctaN]
__device__ __align__(256) float s_nrmP[17*Bsz*4];    // [zi][b][ctaN]

// ---------------- ptx helpers ----------------
__device__ __forceinline__ uint32_t smem_u32(const void* p){
  uint32_t a;
  asm("{ .reg .u64 t; cvta.to.shared.u64 t, %1; cvt.u32.u64 %0, t; }" : "=r"(a) : "l"(p));
  return a;
}
#define CP16(s,g) asm volatile("cp.async.cg.shared.global [%0], [%1], 16;" :: "r"(s), "l"(g))
#define CPCOMMIT() asm volatile("cp.async.commit_group;" ::: "memory")
#define CPWAIT1()  asm volatile("cp.async.wait_group 1;" ::: "memory")

__device__ __forceinline__ void ldsm4(uint32_t* r, uint32_t a){
  asm volatile("ldmatrix.sync.aligned.m8n8.x4.shared.b16 {%0,%1,%2,%3}, [%4];"
    : "=r"(r[0]),"=r"(r[1]),"=r"(r[2]),"=r"(r[3]) : "r"(a));
}
#define MMA(c,a,b0,b1) \
  asm volatile("mma.sync.aligned.m16n8k16.row.col.f32.bf16.bf16.f32 " \
    "{%0,%1,%2,%3},{%4,%5,%6,%7},{%8,%9},{%0,%1,%2,%3};" \
    : "+f"((c)[0]),"+f"((c)[1]),"+f"((c)[2]),"+f"((c)[3]) \
    : "r"((a)[0]),"r"((a)[1]),"r"((a)[2]),"r"((a)[3]),"r"(b0),"r"(b1))

#define SWZ(o) ((o) ^ (((o) >> 3) & 0x70))

// ---------------- fp32 -> bf16 hi/lo split ----------------
__device__ __forceinline__ void split8(const float* __restrict__ s, size_t i,
                                       __nv_bfloat16* __restrict__ h,
                                       __nv_bfloat16* __restrict__ l){
  float4 a = ((const float4*)s)[2*i], b = ((const float4*)s)[2*i+1];
  float v[8] = {a.x,a.y,a.z,a.w,b.x,b.y,b.z,b.w};
  __nv_bfloat162 H[4], L[4];
  #pragma unroll
  for (int j=0;j<4;j++){
    __nv_bfloat16 h0 = __float2bfloat16_rn(v[2*j]);
    __nv_bfloat16 h1 = __float2bfloat16_rn(v[2*j+1]);
    H[j] = __nv_bfloat162(h0, h1);
    L[j] = __nv_bfloat162(__float2bfloat16_rn(v[2*j]   - __bfloat162float(h0)),
                          __float2bfloat16_rn(v[2*j+1] - __bfloat162float(h1)));
  }
  ((uint4*)h)[i] = *(uint4*)H;
  ((uint4*)l)[i] = *(uint4*)L;
}

__global__ void cvt8(const float* __restrict__ s, __nv_bfloat16* __restrict__ h,
                     __nv_bfloat16* __restrict__ l, int n8){
  int i = blockIdx.x*256 + threadIdx.x;
  if (i >= n8) return;
  split8(s, i, h, l);
}

// all 35 weight matrices in one launch (grid exact: 35*32768/256 blocks)
__global__ void cvtW(const float* __restrict__ Wq,  const float* __restrict__ Wkc,
                     const float* __restrict__ Wkp, const float* __restrict__ Wkn,
                     const float* __restrict__ Wfp, const float* __restrict__ Wfn,
                     const float* __restrict__ Wfc,
                     __nv_bfloat16* __restrict__ h, __nv_bfloat16* __restrict__ l){
  const int perW = WSZ/8;
  int i = blockIdx.x*256 + threadIdx.x;
  int w = i / perW, j = i - w*perW;
  const float* src;
  if      (w == 0)  src = Wq;
  else if (w == 1)  src = Wkc;
  else if (w < 10)  src = Wkp + (size_t)(w-2)*WSZ;
  else if (w < 18)  src = Wkn + (size_t)(w-10)*WSZ;
  else if (w < 26)  src = Wfp + (size_t)(w-18)*WSZ;
  else if (w < 34)  src = Wfn + (size_t)(w-26)*WSZ;
  else              src = Wfc;
  split8(src, j, h + (size_t)w*WSZ, l + (size_t)w*WSZ);
}

// =======================================================================
// HMMA GEMM: CTA tile 128(M) x 128(N), 3-term bf16 split.
// Macro k-chunk 32: smem row = [hi 64B | lo 64B], SW128 swizzle.
// grid = (64, 4, nz). 8 warps, warp tile 32x64. 2 CTAs/SM target.
// =======================================================================
template<int MODE>
__global__ __launch_bounds__(256,2) void hgemm(
    const __nv_bfloat16* __restrict__ ah, const __nv_bfloat16* __restrict__ al,
    int lda, int windowed, int zW0,
    const float* __restrict__ bias0, const float* __restrict__ bias1, int bSplit,
    float* __restrict__ out, int ldo, long long oZ,
    const float* __restrict__ Q,
    const float* __restrict__ R,
    float* __restrict__ partial, int pZ0)
{
  const int z = blockIdx.z;
  const int widx = windowed ? (z + (z>=8 ? 1 : 0)) : 0;
  const __nv_bfloat16* Ah = ah + widx*Dd;
  const __nv_bfloat16* Al = al + widx*Dd;
  const __nv_bfloat16* Wh = g_wh + (size_t)(zW0+z)*WSZ;
  const __nv_bfloat16* Wl = g_wl + (size_t)(zW0+z)*WSZ;
  const float* bp = (z < bSplit) ? bias0 + (size_t)z*Dd : bias1 + (size_t)(z-bSplit)*Dd;
  float* outPtr = out ? out + (size_t)widx*Dd + (size_t)z*oZ : nullptr;

  const int tid = threadIdx.x, lane = tid & 31, wid = tid >> 5;
  const int warpM = wid >> 1, warpN = wid & 1;
  const int bBase = blockIdx.x * 128;
  const int nBase = blockIdx.y * 128;

  extern __shared__ char dsm[];
  const uint32_t dynU = (smem_u32(dsm) + 1023u) & ~1023u;
  __shared__ float biasS[128];
  __shared__ float redS[128][2];

  if (tid < 32) ((float4*)biasS)[tid] = ((const float4*)(bp + nBase))[tid];

  float acc[2][8][4];
  #pragma unroll
  for (int m=0;m<2;m++) for (int n=0;n<8;n++) for (int i=0;i<4;i++) acc[m][n][i]=0.f;

  uint32_t aRowOff[2], bRowOff[4];
  #pragma unroll
  for (int i=0;i<2;i++)
    aRowOff[i] = (uint32_t)((warpM*32 + i*16 + (lane&15)) * 128);
  #pragma unroll
  for (int i=0;i<4;i++)
    bRowOff[i] = (uint32_t)((warpN*64 + i*16 + (lane&7) + ((lane&16)>>1)) * 128);
  const int aXb = lane >> 4, bXb = (lane >> 3) & 1, lx = lane & 7;

  // macro stage: A (128 rows, hi|lo in one 128B row) + B likewise
  auto loadStage = [&](int s, int buf){
    const int kOff = s * 32;
    const uint32_t base = dynU + buf*STG;
    #pragma unroll
    for (int i=0;i<4;i++){
      int idx = i*256 + tid, row = idx>>3, u = idx&7;
      const __nv_bfloat16* src = (u < 4) ? Ah : Al;
      CP16(base + SWZ((uint32_t)(row*128 + u*16)),
           src + (size_t)(bBase+row)*(size_t)lda + kOff + (u&3)*8);
    }
    #pragma unroll
    for (int i=0;i<4;i++){
      int idx = i*256 + tid, row = idx>>3, u = idx&7;
      const __nv_bfloat16* src = (u < 4) ? Wh : Wl;
      CP16(base + 16384 + SWZ((uint32_t)(row*128 + u*16)),
           src + (size_t)(nBase+row)*Dd + kOff + (u&3)*8);
    }
  };

  loadStage(0, 0); CPCOMMIT();
  loadStage(1, 1); CPCOMMIT();

  for (int s = 0; s < NST; s++){
    CPWAIT1();
    __syncthreads();
    if (s + 2 < NST) loadStage(s+2, (s+2)%3);
    CPCOMMIT();                      // empty group when no load: keeps wait_group 1 exact
    const uint32_t aB = dynU + (s%3)*STG;
    const uint32_t bB = aB + 16384;
    #pragma unroll
    for (int q=0;q<2;q++){
      const uint32_t hiA = (uint32_t)(((2*q + aXb) ^ lx) << 4);
      const uint32_t hiB = (uint32_t)(((2*q + bXb) ^ lx) << 4);
      const uint32_t loA = (uint32_t)(((4 + 2*q + aXb) ^ lx) << 4);
      const uint32_t loB = (uint32_t)(((4 + 2*q + bXb) ^ lx) << 4);
      uint32_t aH[2][4], bH[4][4], aL[2][4], bL[4][4];
      #pragma unroll
      for (int mt=0;mt<2;mt++) ldsm4(aH[mt], aB + aRowOff[mt] + hiA);
      #pragma unroll
      for (int nt=0;nt<4;nt++) ldsm4(bH[nt], bB + bRowOff[nt] + hiB);
      // Ah * Bh
      #pragma unroll
      for (int mt=0;mt<2;mt++)
        #pragma unroll
        for (int nt=0;nt<4;nt++){
          MMA(acc[mt][nt*2],   aH[mt], bH[nt][0], bH[nt][1]);
          MMA(acc[mt][nt*2+1], aH[mt], bH[nt][2], bH[nt][3]);
        }
      #pragma unroll
      for (int mt=0;mt<2;mt++) ldsm4(aL[mt], aB + aRowOff[mt] + loA);
      // Al * Bh (bH dies after this)
      #pragma unroll
      for (int mt=0;mt<2;mt++)
        #pragma unroll
        for (int nt=0;nt<4;nt++){
          MMA(acc[mt][nt*2],   aL[mt], bH[nt][0], bH[nt][1]);
          MMA(acc[mt][nt*2+1], aL[mt], bH[nt][2], bH[nt][3]);
        }
      #pragma unroll
      for (int nt=0;nt<4;nt++) ldsm4(bL[nt], bB + bRowOff[nt] + loB);
      // Ah * Bl
      #pragma unroll
      for (int mt=0;mt<2;mt++)
        #pragma unroll
        for (int nt=0;nt<4;nt++){
          MMA(acc[mt][nt*2],   aH[mt], bL[nt][0], bL[nt][1]);
          MMA(acc[mt][nt*2+1], aH[mt], bL[nt][2], bL[nt][3]);
        }
    }
  }

  // ---------------- epilogue ----------------
  if constexpr (MODE == M_STORE){
    #pragma unroll
    for (int mt=0;mt<2;mt++){
      const int rl0 = warpM*32 + mt*16 + (lane>>2);
      float* o0 = outPtr + (size_t)(bBase+rl0)*(size_t)ldo;
      float* o1 = o0 + (size_t)8*(size_t)ldo;
      #pragma unroll
      for (int nt=0;nt<8;nt++){
        const int bl = warpN*64 + nt*8 + ((lane&3)<<1);
        const int c  = nBase + bl;
        float bx = biasS[bl], by = biasS[bl+1];
        *(float2*)(o0 + c) = make_float2(acc[mt][nt][0]+bx, acc[mt][nt][1]+by);
        *(float2*)(o1 + c) = make_float2(acc[mt][nt][2]+bx, acc[mt][nt][3]+by);
      }
    }
  }
  else if constexpr (MODE == M_DOT){
    #pragma unroll
    for (int mt=0;mt<2;mt++){
      const int rl0 = warpM*32 + mt*16 + (lane>>2);
      const float* q0 = Q + (size_t)(bBase+rl0)*Dd;
      const float* q1 = q0 + (size_t)8*Dd;
      float s0 = 0.f, s1 = 0.f;
      #pragma unroll
      for (int nt=0;nt<8;nt++){
        const int bl = warpN*64 + nt*8 + ((lane&3)<<1);
        const int c  = nBase + bl;
        float bx = biasS[bl], by = biasS[bl+1];
        float2 qa = *(const float2*)(q0 + c);
        float2 qb = *(const float2*)(q1 + c);
        s0 += (acc[mt][nt][0]+bx)*qa.x + (acc[mt][nt][1]+by)*qa.y;
        s1 += (acc[mt][nt][2]+bx)*qb.x + (acc[mt][nt][3]+by)*qb.y;
      }
      s0 += __shfl_xor_sync(0xffffffffu, s0, 1); s0 += __shfl_xor_sync(0xffffffffu, s0, 2);
      s1 += __shfl_xor_sync(0xffffffffu, s1, 1); s1 += __shfl_xor_sync(0xffffffffu, s1, 2);
      if ((lane&3) == 0){ redS[rl0][warpN] = s0; redS[rl0+8][warpN] = s1; }
    }
    __syncthreads();
    if (tid < 128){
      float p = redS[tid][0] + redS[tid][1];
      partial[((size_t)z*Bsz + bBase + tid)*4 + blockIdx.y] = p;
    }
  }
  else { // M_NORM / M_NORM_RES
    #pragma unroll
    for (int mt=0;mt<2;mt++){
      const int rl0 = warpM*32 + mt*16 + (lane>>2);
      float* o0 = outPtr + (size_t)(bBase+rl0)*(size_t)ldo;
      float* o1 = o0 + (size_t)8*(size_t)ldo;
      const float* r0p = (MODE==M_NORM_RES) ? (R + (size_t)(bBase+rl0)*XS) : nullptr;
      const float* r1p = (MODE==M_NORM_RES) ? (r0p + (size_t)8*XS) : nullptr;
      float s0 = 0.f, s1 = 0.f;
      #pragma unroll
      for (int nt=0;nt<8;nt++){
        const int bl = warpN*64 + nt*8 + ((lane&3)<<1);
        const int c  = nBase + bl;
        float bx = biasS[bl], by = biasS[bl+1];
        float v00 = acc[mt][nt][0]+bx, v01 = acc[mt][nt][1]+by;
        float v10 = acc[mt][nt][2]+bx, v11 = acc[mt][nt][3]+by;
        if constexpr (MODE==M_NORM_RES){
          float2 ra = *(const float2*)(r0p + c);
          float2 rb = *(const float2*)(r1p + c);
          v00 += ra.x; v01 += ra.y; v10 += rb.x; v11 += rb.y;
        }
        *(float2*)(o0 + c) = make_float2(v00, v01);
        *(float2*)(o1 + c) = make_float2(v10, v11);
        s0 += v00*v00 + v01*v01;
        s1 += v10*v10 + v11*v11;
      }
      s0 += __shfl_xor_sync(0xffffffffu, s0, 1); s0 += __shfl_xor_sync(0xffffffffu, s0, 2);
      s1 += __shfl_xor_sync(0xffffffffu, s1, 1); s1 += __shfl_xor_sync(0xffffffffu, s1, 2);
      if ((lane&3) == 0){ redS[rl0][warpN] = s0; redS[rl0+8][warpN] = s1; }
    }
    __syncthreads();
    if (tid < 128){
      float p = redS[tid][0] + redS[tid][1];
      partial[((size_t)(pZ0+z)*Bsz + bBase + tid)*4 + blockIdx.y] = p;
    }
  }
}

// =======================================================================
// second pass: per-row l2 normalization in-place on out, 17 segments
// =======================================================================
__global__ void norm_scale(float* __restrict__ out, const float* __restrict__ partial){
  const int b = blockIdx.x, zi = blockIdx.y, t = threadIdx.x;
  const float* p = partial + ((size_t)zi*Bsz + b)*4;
  float ss = p[0]+p[1]+p[2]+p[3];
  float sc = 1.f / fmaxf(sqrtf(ss), 1e-12f);
  int col0 = (zi==16) ? 4096 : ((zi<8) ? zi*512 : (zi+1)*512);
  float4* row = (float4*)(out + (size_t)b*XS + col0);
  float4 v = row[t];
  v.x*=sc; v.y*=sc; v.z*=sc; v.w*=sc;
  row[t] = v;
}

// =======================================================================
// mix: attn = q.kc; v = l2norm(xc*attn + sum_w ap*xp_w + sum_w an*xn_w)
// =======================================================================
__global__ void mix_kernel(const float* __restrict__ x, float* __restrict__ outv,
                           const float* __restrict__ q, const float* __restrict__ kc,
                           const float* __restrict__ dotP)
{
  __shared__ float sb[4];
  const int b = blockIdx.x, t = threadIdx.x;
  const float4* xr = (const float4*)(x + (size_t)b*XS);

  float4 q4 = ((const float4*)(q  + (size_t)b*Dd))[t];
  float4 k4 = ((const float4*)(kc + (size_t)b*Dd))[t];
  float part = q4.x*k4.x + q4.y*k4.y + q4.z*k4.z + q4.w*k4.w;
  #pragma unroll
  for (int o=16;o;o>>=1) part += __shfl_xor_sync(0xffffffffu, part, o);
  if ((t & 31) == 0) sb[t>>5] = part;
  __syncthreads();
  const float attn = sb[0] + sb[1] + sb[2] + sb[3];
  __syncthreads();

  float4 xc4 = xr[1024 + t];
  float4 acc;
  acc.x = xc4.x*attn; acc.y = xc4.y*attn; acc.z = xc4.z*attn; acc.w = xc4.w*attn;
  #pragma unroll
  for (int w=0;w<8;w++){
    float4 pa = *(const float4*)(dotP + ((size_t)w*Bsz + b)*4);
    float aw = pa.x + pa.y + pa.z + pa.w;
    float4 p4 = xr[w*128 + t];
    acc.x += aw*p4.x; acc.y += aw*p4.y; acc.z += aw*p4.z; acc.w += aw*p4.w;
    float4 pn = *(const float4*)(dotP + ((size_t)(8+w)*Bsz + b)*4);
    float nw = pn.x + pn.y + pn.z + pn.w;
    float4 n4 = xr[(9+w)*128 + t];
    acc.x += nw*n4.x; acc.y += nw*n4.y; acc.z += nw*n4.z; acc.w += nw*n4.w;
  }
  float ss = acc.x*acc.x + acc.y*acc.y + acc.z*acc.z + acc.w*acc.w;
  #pragma unroll
  for (int o=16;o;o>>=1) ss += __shfl_xor_sync(0xffffffffu, ss, o);
  if ((t & 31) == 0) sb[t>>5] = ss;
  __syncthreads();
  float tot = sb[0] + sb[1] + sb[2] + sb[3];
  float sc = 1.f / fmaxf(sqrtf(tot), 1e-12f);
  float4 v; v.x = acc.x*sc; v.y = acc.y*sc; v.z = acc.z*sc; v.w = acc.w*sc;
  ((float4*)(outv + (size_t)b*Dd))[t] = v;
}

// =======================================================================
extern "C" void kernel_launch(void* const* d_in, const int* in_sizes, int n_in,
                              void* d_out, int out_size)
{
  const float* x   = (const float*)d_in[0];
  const float* Wq  = (const float*)d_in[1];
  const float* bq  = (const float*)d_in[2];
  const float* Wkc = (const float*)d_in[3];
  const float* bkc = (const float*)d_in[4];
  const float* Wkp = (const float*)d_in[5];
  const float* bkp = (const float*)d_in[6];
  const float* Wkn = (const float*)d_in[7];
  const float* bkn = (const float*)d_in[8];
  const float* Wfp = (const float*)d_in[9];
  const float* bfp = (const float*)d_in[10];
  const float* Wfn = (const float*)d_in[11];
  const float* bfn = (const float*)d_in[12];
  const float* Wfc = (const float*)d_in[13];
  const float* bfc = (const float*)d_in[14];
  float* out = (float*)d_out;

  __nv_bfloat16 *xh, *xl, *vh, *vl, *wh, *wl;
  float *qkc, *v, *dotP, *nrmP;
  cudaGetSymbolAddress((void**)&xh, g_xh);
  cudaGetSymbolAddress((void**)&xl, g_xl);
  cudaGetSymbolAddress((void**)&wh, g_wh);
  cudaGetSymbolAddress((void**)&wl, g_wl);
  cudaGetSymbolAddress((void**)&vh, g_vh);
  cudaGetSymbolAddress((void**)&vl, g_vl);
  cudaGetSymbolAddress((void**)&qkc,  s_qkc);
  cudaGetSymbolAddress((void**)&v,    s_v);
  cudaGetSymbolAddress((void**)&dotP, s_dotP);
  cudaGetSymbolAddress((void**)&nrmP, s_nrmP);
  float* q  = qkc;
  float* kc = qkc + (size_t)Bsz*Dd;

  cudaFuncSetAttribute(hgemm<M_STORE>,    cudaFuncAttributeMaxDynamicSharedMemorySize, DYN_SMEM);
  cudaFuncSetAttribute(hgemm<M_DOT>,      cudaFuncAttributeMaxDynamicSharedMemorySize, DYN_SMEM);
  cudaFuncSetAttribute(hgemm<M_NORM>,     cudaFuncAttributeMaxDynamicSharedMemorySize, DYN_SMEM);
  cudaFuncSetAttribute(hgemm<M_NORM_RES>, cudaFuncAttributeMaxDynamicSharedMemorySize, DYN_SMEM);

  // [0] x -> hi/lo
  { int n8 = (Bsz*XS)/8; cvt8<<<(n8+255)/256, 256>>>(x, xh, xl, n8); }
  // [1] all 35 weights -> hi/lo, one launch
  cvtW<<<(NW*(WSZ/8))/256, 256>>>(Wq, Wkc, Wkp, Wkn, Wfp, Wfn, Wfc, wh, wl);

  // [2] q / kc
  hgemm<M_STORE><<<dim3(64,4,2), 256, DYN_SMEM>>>(
      xh+4096, xl+4096, XS, 0, 0, bq, bkc, 1,
      qkc, Dd, (long long)Bsz*Dd, nullptr, nullptr, nullptr, 0);

  // [3] ap/an partial dots (kp/kn never materialized)
  hgemm<M_DOT><<<dim3(64,4,16), 256, DYN_SMEM>>>(
      xh, xl, XS, 1, 2, bkp, bkn, 8,
      nullptr, 0, 0, q, nullptr, dotP, 0);

  // [4] mix -> v
  mix_kernel<<<Bsz, 128>>>(x, v, q, kc, dotP);

  // [5] fp/fn raw + sumsq partials, straight into d_out  (profiled launch)
  hgemm<M_NORM><<<dim3(64,4,16), 256, DYN_SMEM>>>(
      xh, xl, XS, 1, 18, bfp, bfn, 8,
      out, XS, 0, nullptr, nullptr, nrmP, 0);

  // [6] convert v
  { int n8 = (Bsz*Dd)/8; cvt8<<<(n8+255)/256, 256>>>(v, vh, vl, n8); }

  // [7] fc (+ residual xc) raw + partials
  hgemm<M_NORM_RES><<<dim3(64,4,1), 256, DYN_SMEM>>>(
      vh, vl, Dd, 0, 34, bfc, bfc, 1,
      out+4096, XS, 0, nullptr, x+4096, nrmP, 16);

  // [8] in-place l2 normalization of all 17 segments
  norm_scale<<<dim3(Bsz,17), 128>>>(out, nrmP);
}

// round 6
// speedup vs baseline: 5.0218x; 1.3396x over previous
#include <cuda_runtime.h>
#include <cuda_fp16.h>
#include <cstdint>

#define Bsz 8192
#define Dd  512
#define XS  8704           // 17*512 row stride of x / out
#define WSZ 262144         // 512*512 per weight matrix
#define NW  35
#define NST 8              // 8 macro k-chunks of 64 (2 fp16 terms per chunk)
#define STG 49152          // per-stage smem: A-hi 16K + A-lo 16K + B 16K
#define DYN_SMEM (2*STG + 1024)

enum { M_STORE=0, M_DOT=1, M_NORM=2, M_NORM_RES=3 };

// ---------------- device scratch (allocation-free rule) ----------------
__device__ __align__(256) __half g_xh[Bsz*XS];
__device__ __align__(256) __half g_xl[Bsz*XS];
__device__ __align__(256) __half g_wh[NW*WSZ];
__device__ __align__(256) __half g_vh[Bsz*Dd];
__device__ __align__(256) __half g_vl[Bsz*Dd];
__device__ __align__(256) float s_qkc[2*Bsz*Dd];     // q then kc
__device__ __align__(256) float s_v[Bsz*Dd];
__device__ __align__(256) float s_dotP[16*Bsz*4];    // [z][b][ctaN]
__device__ __align__(256) float s_nrmP[17*Bsz*4];    // [zi][b][ctaN]

// ---------------- ptx helpers ----------------
__device__ __forceinline__ uint32_t smem_u32(const void* p){
  uint32_t a;
  asm("{ .reg .u64 t; cvta.to.shared.u64 t, %1; cvt.u32.u64 %0, t; }" : "=r"(a) : "l"(p));
  return a;
}
#define CP16(s,g) asm volatile("cp.async.cg.shared.global [%0], [%1], 16;" :: "r"(s), "l"(g))
#define CPCOMMIT() asm volatile("cp.async.commit_group;" ::: "memory")
#define CPWAIT1()  asm volatile("cp.async.wait_group 1;" ::: "memory")

__device__ __forceinline__ void ldsm4(uint32_t* r, uint32_t a){
  asm volatile("ldmatrix.sync.aligned.m8n8.x4.shared.b16 {%0,%1,%2,%3}, [%4];"
    : "=r"(r[0]),"=r"(r[1]),"=r"(r[2]),"=r"(r[3]) : "r"(a));
}
#define MMA(c,a,b0,b1) \
  asm volatile("mma.sync.aligned.m16n8k16.row.col.f32.f16.f16.f32 " \
    "{%0,%1,%2,%3},{%4,%5,%6,%7},{%8,%9},{%0,%1,%2,%3};" \
    : "+f"((c)[0]),"+f"((c)[1]),"+f"((c)[2]),"+f"((c)[3]) \
    : "r"((a)[0]),"r"((a)[1]),"r"((a)[2]),"r"((a)[3]),"r"(b0),"r"(b1))

#define SWZ(o) ((o) ^ (((o) >> 3) & 0x70))

// ---------------- fp32 -> fp16 hi/lo split ----------------
__device__ __forceinline__ void split8(const float* __restrict__ s, size_t i,
                                       __half* __restrict__ h,
                                       __half* __restrict__ l){
  float4 a = ((const float4*)s)[2*i], b = ((const float4*)s)[2*i+1];
  float v[8] = {a.x,a.y,a.z,a.w,b.x,b.y,b.z,b.w};
  __half2 H[4], L[4];
  #pragma unroll
  for (int j=0;j<4;j++){
    __half h0 = __float2half_rn(v[2*j]);
    __half h1 = __float2half_rn(v[2*j+1]);
    H[j] = __half2(h0, h1);
    L[j] = __half2(__float2half_rn(v[2*j]   - __half2float(h0)),
                   __float2half_rn(v[2*j+1] - __half2float(h1)));
  }
  ((uint4*)h)[i] = *(uint4*)H;
  ((uint4*)l)[i] = *(uint4*)L;
}

__global__ void cvt8(const float* __restrict__ s, __half* __restrict__ h,
                     __half* __restrict__ l, int n8){
  int i = blockIdx.x*256 + threadIdx.x;
  if (i >= n8) return;
  split8(s, i, h, l);
}

// all 35 weight matrices -> single fp16 (hi only), one launch
__global__ void cvtW(const float* __restrict__ Wq,  const float* __restrict__ Wkc,
                     const float* __restrict__ Wkp, const float* __restrict__ Wkn,
                     const float* __restrict__ Wfp, const float* __restrict__ Wfn,
                     const float* __restrict__ Wfc, __half* __restrict__ h){
  const int perW = WSZ/8;
  int i = blockIdx.x*256 + threadIdx.x;
  int w = i / perW, j = i - w*perW;
  const float* src;
  if      (w == 0)  src = Wq;
  else if (w == 1)  src = Wkc;
  else if (w < 10)  src = Wkp + (size_t)(w-2)*WSZ;
  else if (w < 18)  src = Wkn + (size_t)(w-10)*WSZ;
  else if (w < 26)  src = Wfp + (size_t)(w-18)*WSZ;
  else if (w < 34)  src = Wfn + (size_t)(w-26)*WSZ;
  else              src = Wfc;
  float4 a = ((const float4*)src)[2*j], b = ((const float4*)src)[2*j+1];
  __half2 H[4];
  H[0] = __half2(__float2half_rn(a.x), __float2half_rn(a.y));
  H[1] = __half2(__float2half_rn(a.z), __float2half_rn(a.w));
  H[2] = __half2(__float2half_rn(b.x), __float2half_rn(b.y));
  H[3] = __half2(__float2half_rn(b.z), __float2half_rn(b.w));
  ((uint4*)(h + (size_t)w*WSZ))[j] = *(uint4*)H;
}

// =======================================================================
// HMMA GEMM: CTA tile 128(M) x 128(N), fp16 2-term split (A=hi+lo, W=hi).
// Macro k-chunk 64. grid = (64, 4, nz). 8 warps, warp tile 32x64. 2 CTA/SM.
// =======================================================================
template<int MODE>
__global__ __launch_bounds__(256,2) void hgemm(
    const __half* __restrict__ ah, const __half* __restrict__ al,
    int lda, int windowed, int zW0,
    const float* __restrict__ bias0, const float* __restrict__ bias1, int bSplit,
    float* __restrict__ out, int ldo, long long oZ,
    const float* __restrict__ Q,
    const float* __restrict__ R,
    float* __restrict__ partial, int pZ0)
{
  const int z = blockIdx.z;
  const int widx = windowed ? (z + (z>=8 ? 1 : 0)) : 0;
  const __half* Ah = ah + widx*Dd;
  const __half* Al = al + widx*Dd;
  const __half* Wh = g_wh + (size_t)(zW0+z)*WSZ;
  const float* bp = (z < bSplit) ? bias0 + (size_t)z*Dd : bias1 + (size_t)(z-bSplit)*Dd;
  float* outPtr = out ? out + (size_t)widx*Dd + (size_t)z*oZ : nullptr;

  const int tid = threadIdx.x, lane = tid & 31, wid = tid >> 5;
  const int warpM = wid >> 1, warpN = wid & 1;
  const int bBase = blockIdx.x * 128;
  const int nBase = blockIdx.y * 128;

  extern __shared__ char dsm[];
  const uint32_t dynU = (smem_u32(dsm) + 1023u) & ~1023u;
  __shared__ float biasS[128];
  __shared__ float redS[128][2];

  if (tid < 32) ((float4*)biasS)[tid] = ((const float4*)(bp + nBase))[tid];

  float acc[2][8][4];
  #pragma unroll
  for (int m=0;m<2;m++) for (int n=0;n<8;n++) for (int i=0;i<4;i++) acc[m][n][i]=0.f;

  uint32_t aRowOff[2], bRowOff[4];
  #pragma unroll
  for (int i=0;i<2;i++)
    aRowOff[i] = (uint32_t)((warpM*32 + i*16 + (lane&15)) * 128);
  #pragma unroll
  for (int i=0;i<4;i++)
    bRowOff[i] = (uint32_t)((warpN*64 + i*16 + (lane&7) + ((lane&16)>>1)) * 128);
  const int aXb = lane >> 4, bXb = (lane >> 3) & 1, lx = lane & 7;

  // macro stage: A-hi 128x64 (16KB) | A-lo (16KB) | B 128x64 (16KB)
  auto loadStage = [&](int s, int buf){
    const int kOff = s * 64;
    const uint32_t base = dynU + buf*STG;
    #pragma unroll
    for (int i=0;i<4;i++){
      int idx = i*256 + tid, row = idx>>3, g = idx&7;
      uint32_t sw = SWZ((uint32_t)(row*128 + g*16));
      size_t go = (size_t)(bBase+row)*(size_t)lda + kOff + g*8;
      CP16(base + sw,         Ah + go);
      CP16(base + 16384 + sw, Al + go);
    }
    #pragma unroll
    for (int i=0;i<4;i++){
      int idx = i*256 + tid, row = idx>>3, g = idx&7;
      CP16(base + 32768 + SWZ((uint32_t)(row*128 + g*16)),
           Wh + (size_t)(nBase+row)*Dd + kOff + g*8);
    }
  };

  loadStage(0, 0); CPCOMMIT();
  loadStage(1, 1); CPCOMMIT();

  for (int s = 0; s < NST; s++){
    CPWAIT1();
    __syncthreads();
    const uint32_t aB = dynU + (s&1)*STG;
    const uint32_t lB = aB + 16384;
    const uint32_t bB = aB + 32768;
    #pragma unroll
    for (int q=0;q<4;q++){
      const uint32_t selA = (uint32_t)(((2*q + aXb) ^ lx) << 4);
      const uint32_t selB = (uint32_t)(((2*q + bXb) ^ lx) << 4);
      uint32_t aH[2][4], aL[2][4], bF[4][4];
      #pragma unroll
      for (int mt=0;mt<2;mt++) ldsm4(aH[mt], aB + aRowOff[mt] + selA);
      #pragma unroll
      for (int nt=0;nt<4;nt++) ldsm4(bF[nt], bB + bRowOff[nt] + selB);
      // Ah * B
      #pragma unroll
      for (int mt=0;mt<2;mt++)
        #pragma unroll
        for (int nt=0;nt<4;nt++){
          MMA(acc[mt][nt*2],   aH[mt], bF[nt][0], bF[nt][1]);
          MMA(acc[mt][nt*2+1], aH[mt], bF[nt][2], bF[nt][3]);
        }
      #pragma unroll
      for (int mt=0;mt<2;mt++) ldsm4(aL[mt], lB + aRowOff[mt] + selA);
      // Al * B
      #pragma unroll
      for (int mt=0;mt<2;mt++)
        #pragma unroll
        for (int nt=0;nt<4;nt++){
          MMA(acc[mt][nt*2],   aL[mt], bF[nt][0], bF[nt][1]);
          MMA(acc[mt][nt*2+1], aL[mt], bF[nt][2], bF[nt][3]);
        }
    }
    __syncthreads();
    if (s + 2 < NST) loadStage(s+2, s&1);
    CPCOMMIT();                       // empty group when no load keeps count exact
  }

  // ---------------- epilogue ----------------
  if constexpr (MODE == M_STORE){
    #pragma unroll
    for (int mt=0;mt<2;mt++){
      const int rl0 = warpM*32 + mt*16 + (lane>>2);
      float* o0 = outPtr + (size_t)(bBase+rl0)*(size_t)ldo;
      float* o1 = o0 + (size_t)8*(size_t)ldo;
      #pragma unroll
      for (int nt=0;nt<8;nt++){
        const int bl = warpN*64 + nt*8 + ((lane&3)<<1);
        const int c  = nBase + bl;
        float bx = biasS[bl], by = biasS[bl+1];
        *(float2*)(o0 + c) = make_float2(acc[mt][nt][0]+bx, acc[mt][nt][1]+by);
        *(float2*)(o1 + c) = make_float2(acc[mt][nt][2]+bx, acc[mt][nt][3]+by);
      }
    }
  }
  else if constexpr (MODE == M_DOT){
    #pragma unroll
    for (int mt=0;mt<2;mt++){
      const int rl0 = warpM*32 + mt*16 + (lane>>2);
      const float* q0 = Q + (size_t)(bBase+rl0)*Dd;
      const float* q1 = q0 + (size_t)8*Dd;
      float s0 = 0.f, s1 = 0.f;
      #pragma unroll
      for (int nt=0;nt<8;nt++){
        const int bl = warpN*64 + nt*8 + ((lane&3)<<1);
        const int c  = nBase + bl;
        float bx = biasS[bl], by = biasS[bl+1];
        float2 qa = *(const float2*)(q0 + c);
        float2 qb = *(const float2*)(q1 + c);
        s0 += (acc[mt][nt][0]+bx)*qa.x + (acc[mt][nt][1]+by)*qa.y;
        s1 += (acc[mt][nt][2]+bx)*qb.x + (acc[mt][nt][3]+by)*qb.y;
      }
      s0 += __shfl_xor_sync(0xffffffffu, s0, 1); s0 += __shfl_xor_sync(0xffffffffu, s0, 2);
      s1 += __shfl_xor_sync(0xffffffffu, s1, 1); s1 += __shfl_xor_sync(0xffffffffu, s1, 2);
      if ((lane&3) == 0){ redS[rl0][warpN] = s0; redS[rl0+8][warpN] = s1; }
    }
    __syncthreads();
    if (tid < 128){
      float p = redS[tid][0] + redS[tid][1];
      partial[((size_t)z*Bsz + bBase + tid)*4 + blockIdx.y] = p;
    }
  }
  else { // M_NORM / M_NORM_RES
    #pragma unroll
    for (int mt=0;mt<2;mt++){
      const int rl0 = warpM*32 + mt*16 + (lane>>2);
      float* o0 = outPtr + (size_t)(bBase+rl0)*(size_t)ldo;
      float* o1 = o0 + (size_t)8*(size_t)ldo;
      const float* r0p = (MODE==M_NORM_RES) ? (R + (size_t)(bBase+rl0)*XS) : nullptr;
      const float* r1p = (MODE==M_NORM_RES) ? (r0p + (size_t)8*XS) : nullptr;
      float s0 = 0.f, s1 = 0.f;
      #pragma unroll
      for (int nt=0;nt<8;nt++){
        const int bl = warpN*64 + nt*8 + ((lane&3)<<1);
        const int c  = nBase + bl;
        float bx = biasS[bl], by = biasS[bl+1];
        float v00 = acc[mt][nt][0]+bx, v01 = acc[mt][nt][1]+by;
        float v10 = acc[mt][nt][2]+bx, v11 = acc[mt][nt][3]+by;
        if constexpr (MODE==M_NORM_RES){
          float2 ra = *(const float2*)(r0p + c);
          float2 rb = *(const float2*)(r1p + c);
          v00 += ra.x; v01 += ra.y; v10 += rb.x; v11 += rb.y;
        }
        *(float2*)(o0 + c) = make_float2(v00, v01);
        *(float2*)(o1 + c) = make_float2(v10, v11);
        s0 += v00*v00 + v01*v01;
        s1 += v10*v10 + v11*v11;
      }
      s0 += __shfl_xor_sync(0xffffffffu, s0, 1); s0 += __shfl_xor_sync(0xffffffffu, s0, 2);
      s1 += __shfl_xor_sync(0xffffffffu, s1, 1); s1 += __shfl_xor_sync(0xffffffffu, s1, 2);
      if ((lane&3) == 0){ redS[rl0][warpN] = s0; redS[rl0+8][warpN] = s1; }
    }
    __syncthreads();
    if (tid < 128){
      float p = redS[tid][0] + redS[tid][1];
      partial[((size_t)(pZ0+z)*Bsz + bBase + tid)*4 + blockIdx.y] = p;
    }
  }
}

// =======================================================================
// second pass: per-row l2 normalization in-place on out, 17 segments
// =======================================================================
__global__ void norm_scale(float* __restrict__ out, const float* __restrict__ partial){
  const int b = blockIdx.x, zi = blockIdx.y, t = threadIdx.x;
  const float* p = partial + ((size_t)zi*Bsz + b)*4;
  float ss = p[0]+p[1]+p[2]+p[3];
  float sc = 1.f / fmaxf(sqrtf(ss), 1e-12f);
  int col0 = (zi==16) ? 4096 : ((zi<8) ? zi*512 : (zi+1)*512);
  float4* row = (float4*)(out + (size_t)b*XS + col0);
  float4 v = row[t];
  v.x*=sc; v.y*=sc; v.z*=sc; v.w*=sc;
  row[t] = v;
}

// =======================================================================
// mix: attn = q.kc; v = l2norm(xc*attn + sum_w ap*xp_w + sum_w an*xn_w)
// =======================================================================
__global__ void mix_kernel(const float* __restrict__ x, float* __restrict__ outv,
                           const float* __restrict__ q, const float* __restrict__ kc,
                           const float* __restrict__ dotP)
{
  __shared__ float sb[4];
  const int b = blockIdx.x, t = threadIdx.x;
  const float4* xr = (const float4*)(x + (size_t)b*XS);

  float4 q4 = ((const float4*)(q  + (size_t)b*Dd))[t];
  float4 k4 = ((const float4*)(kc + (size_t)b*Dd))[t];
  float part = q4.x*k4.x + q4.y*k4.y + q4.z*k4.z + q4.w*k4.w;
  #pragma unroll
  for (int o=16;o;o>>=1) part += __shfl_xor_sync(0xffffffffu, part, o);
  if ((t & 31) == 0) sb[t>>5] = part;
  __syncthreads();
  const float attn = sb[0] + sb[1] + sb[2] + sb[3];
  __syncthreads();

  float4 xc4 = xr[1024 + t];
  float4 acc;
  acc.x = xc4.x*attn; acc.y = xc4.y*attn; acc.z = xc4.z*attn; acc.w = xc4.w*attn;
  #pragma unroll
  for (int w=0;w<8;w++){
    float4 pa = *(const float4*)(dotP + ((size_t)w*Bsz + b)*4);
    float aw = pa.x + pa.y + pa.z + pa.w;
    float4 p4 = xr[w*128 + t];
    acc.x += aw*p4.x; acc.y += aw*p4.y; acc.z += aw*p4.z; acc.w += aw*p4.w;
    float4 pn = *(const float4*)(dotP + ((size_t)(8+w)*Bsz + b)*4);
    float nw = pn.x + pn.y + pn.z + pn.w;
    float4 n4 = xr[(9+w)*128 + t];
    acc.x += nw*n4.x; acc.y += nw*n4.y; acc.z += nw*n4.z; acc.w += nw*n4.w;
  }
  float ss = acc.x*acc.x + acc.y*acc.y + acc.z*acc.z + acc.w*acc.w;
  #pragma unroll
  for (int o=16;o;o>>=1) ss += __shfl_xor_sync(0xffffffffu, ss, o);
  if ((t & 31) == 0) sb[t>>5] = ss;
  __syncthreads();
  float tot = sb[0] + sb[1] + sb[2] + sb[3];
  float sc = 1.f / fmaxf(sqrtf(tot), 1e-12f);
  float4 v; v.x = acc.x*sc; v.y = acc.y*sc; v.z = acc.z*sc; v.w = acc.w*sc;
  ((float4*)(outv + (size_t)b*Dd))[t] = v;
}

// =======================================================================
extern "C" void kernel_launch(void* const* d_in, const int* in_sizes, int n_in,
                              void* d_out, int out_size)
{
  const float* x   = (const float*)d_in[0];
  const float* Wq  = (const float*)d_in[1];
  const float* bq  = (const float*)d_in[2];
  const float* Wkc = (const float*)d_in[3];
  const float* bkc = (const float*)d_in[4];
  const float* Wkp = (const float*)d_in[5];
  const float* bkp = (const float*)d_in[6];
  const float* Wkn = (const float*)d_in[7];
  const float* bkn = (const float*)d_in[8];
  const float* Wfp = (const float*)d_in[9];
  const float* bfp = (const float*)d_in[10];
  const float* Wfn = (const float*)d_in[11];
  const float* bfn = (const float*)d_in[12];
  const float* Wfc = (const float*)d_in[13];
  const float* bfc = (const float*)d_in[14];
  float* out = (float*)d_out;

  __half *xh, *xl, *vh, *vl, *wh;
  float *qkc, *v, *dotP, *nrmP;
  cudaGetSymbolAddress((void**)&xh, g_xh);
  cudaGetSymbolAddress((void**)&xl, g_xl);
  cudaGetSymbolAddress((void**)&wh, g_wh);
  cudaGetSymbolAddress((void**)&vh, g_vh);
  cudaGetSymbolAddress((void**)&vl, g_vl);
  cudaGetSymbolAddress((void**)&qkc,  s_qkc);
  cudaGetSymbolAddress((void**)&v,    s_v);
  cudaGetSymbolAddress((void**)&dotP, s_dotP);
  cudaGetSymbolAddress((void**)&nrmP, s_nrmP);
  float* q  = qkc;
  float* kc = qkc + (size_t)Bsz*Dd;

  cudaFuncSetAttribute(hgemm<M_STORE>,    cudaFuncAttributeMaxDynamicSharedMemorySize, DYN_SMEM);
  cudaFuncSetAttribute(hgemm<M_DOT>,      cudaFuncAttributeMaxDynamicSharedMemorySize, DYN_SMEM);
  cudaFuncSetAttribute(hgemm<M_NORM>,     cudaFuncAttributeMaxDynamicSharedMemorySize, DYN_SMEM);
  cudaFuncSetAttribute(hgemm<M_NORM_RES>, cudaFuncAttributeMaxDynamicSharedMemorySize, DYN_SMEM);

  // [0] x -> fp16 hi/lo
  { int n8 = (Bsz*XS)/8; cvt8<<<(n8+255)/256, 256>>>(x, xh, xl, n8); }
  // [1] all 35 weights -> fp16 (hi only), one launch
  cvtW<<<(NW*(WSZ/8))/256, 256>>>(Wq, Wkc, Wkp, Wkn, Wfp, Wfn, Wfc, wh);

  // [2] q / kc
  hgemm<M_STORE><<<dim3(64,4,2), 256, DYN_SMEM>>>(
      xh+4096, xl+4096, XS, 0, 0, bq, bkc, 1,
      qkc, Dd, (long long)Bsz*Dd, nullptr, nullptr, nullptr, 0);

  // [3] ap/an partial dots (kp/kn never materialized)
  hgemm<M_DOT><<<dim3(64,4,16), 256, DYN_SMEM>>>(
      xh, xl, XS, 1, 2, bkp, bkn, 8,
      nullptr, 0, 0, q, nullptr, dotP, 0);

  // [4] mix -> v
  mix_kernel<<<Bsz, 128>>>(x, v, q, kc, dotP);

  // [5] fp/fn raw + sumsq partials, straight into d_out
  hgemm<M_NORM><<<dim3(64,4,16), 256, DYN_SMEM>>>(
      xh, xl, XS, 1, 18, bfp, bfn, 8,
      out, XS, 0, nullptr, nullptr, nrmP, 0);

  // [6] convert v -> fp16 hi/lo
  { int n8 = (Bsz*Dd)/8; cvt8<<<(n8+255)/256, 256>>>(v, vh, vl, n8); }

  // [7] fc (+ residual xc) raw + partials
  hgemm<M_NORM_RES><<<dim3(64,4,1), 256, DYN_SMEM>>>(
      vh, vl, Dd, 0, 34, bfc, bfc, 1,
      out+4096, XS, 0, nullptr, x+4096, nrmP, 16);

  // [8] in-place l2 normalization of all 17 segments
  norm_scale<<<dim3(Bsz,17), 128>>>(out, nrmP);
}

// round 7
// speedup vs baseline: 7.3771x; 1.4690x over previous
#include <cuda_runtime.h>
#include <cuda_fp16.h>
#include <cstdint>

#define Bsz 8192
#define Dd  512
#define XS  8704           // 17*512 row stride of x / out
#define WSZ 262144         // 512*512 per weight matrix
#define NW  35
#define NST 8              // 8 k-chunks of 64
#define STG 32768          // per-stage smem: A 16K + B 16K
#define DYN_SMEM (3*STG + 1024)

enum { M_STORE=0, M_DOT=1, M_NORM=2, M_NORM_RES=3 };

// ---------------- device scratch (allocation-free rule) ----------------
__device__ __align__(256) __half g_xh[Bsz*XS];
__device__ __align__(256) __half g_wh[NW*WSZ];
__device__ __align__(256) __half g_vh[Bsz*Dd];
__device__ __align__(256) float s_qkc[2*Bsz*Dd];     // q then kc
__device__ __align__(256) float s_v[Bsz*Dd];
__device__ __align__(256) float s_dotP[16*Bsz*4];    // [z][b][ctaN]
__device__ __align__(256) float s_nrmP[17*Bsz*4];    // [zi][b][ctaN]

// ---------------- ptx helpers ----------------
__device__ __forceinline__ uint32_t smem_u32(const void* p){
  uint32_t a;
  asm("{ .reg .u64 t; cvta.to.shared.u64 t, %1; cvt.u32.u64 %0, t; }" : "=r"(a) : "l"(p));
  return a;
}
#define CP16(s,g) asm volatile("cp.async.cg.shared.global [%0], [%1], 16;" :: "r"(s), "l"(g))
#define CPCOMMIT() asm volatile("cp.async.commit_group;" ::: "memory")
#define CPWAIT1()  asm volatile("cp.async.wait_group 1;" ::: "memory")

__device__ __forceinline__ void ldsm4(uint32_t* r, uint32_t a){
  asm volatile("ldmatrix.sync.aligned.m8n8.x4.shared.b16 {%0,%1,%2,%3}, [%4];"
    : "=r"(r[0]),"=r"(r[1]),"=r"(r[2]),"=r"(r[3]) : "r"(a));
}
#define MMA(c,a,b0,b1) \
  asm volatile("mma.sync.aligned.m16n8k16.row.col.f32.f16.f16.f32 " \
    "{%0,%1,%2,%3},{%4,%5,%6,%7},{%8,%9},{%0,%1,%2,%3};" \
    : "+f"((c)[0]),"+f"((c)[1]),"+f"((c)[2]),"+f"((c)[3]) \
    : "r"((a)[0]),"r"((a)[1]),"r"((a)[2]),"r"((a)[3]),"r"(b0),"r"(b1))

#define SWZ(o) ((o) ^ (((o) >> 3) & 0x70))

// ---------------- fp32 -> fp16 (round-to-nearest) ----------------
__device__ __forceinline__ void cvt8core(const float* __restrict__ s, size_t i,
                                         __half* __restrict__ h){
  float4 a = ((const float4*)s)[2*i], b = ((const float4*)s)[2*i+1];
  __half2 H[4];
  H[0] = __half2(__float2half_rn(a.x), __float2half_rn(a.y));
  H[1] = __half2(__float2half_rn(a.z), __float2half_rn(a.w));
  H[2] = __half2(__float2half_rn(b.x), __float2half_rn(b.y));
  H[3] = __half2(__float2half_rn(b.z), __float2half_rn(b.w));
  ((uint4*)h)[i] = *(uint4*)H;
}

__global__ void cvtH(const float* __restrict__ s, __half* __restrict__ h, int n8){
  int i = blockIdx.x*256 + threadIdx.x;
  if (i >= n8) return;
  cvt8core(s, i, h);
}

// all 35 weight matrices -> fp16, one launch
__global__ void cvtW(const float* __restrict__ Wq,  const float* __restrict__ Wkc,
                     const float* __restrict__ Wkp, const float* __restrict__ Wkn,
                     const float* __restrict__ Wfp, const float* __restrict__ Wfn,
                     const float* __restrict__ Wfc, __half* __restrict__ h){
  const int perW = WSZ/8;
  int i = blockIdx.x*256 + threadIdx.x;
  int w = i / perW, j = i - w*perW;
  const float* src;
  if      (w == 0)  src = Wq;
  else if (w == 1)  src = Wkc;
  else if (w < 10)  src = Wkp + (size_t)(w-2)*WSZ;
  else if (w < 18)  src = Wkn + (size_t)(w-10)*WSZ;
  else if (w < 26)  src = Wfp + (size_t)(w-18)*WSZ;
  else if (w < 34)  src = Wfn + (size_t)(w-26)*WSZ;
  else              src = Wfc;
  cvt8core(src, j, h + (size_t)w*WSZ);
}

// =======================================================================
// HMMA GEMM: CTA tile 128(M) x 128(N), single fp16 term, k-chunk 64,
// 3-stage cp.async pipeline, one sync per chunk.
// grid = (64, 4, nz). 8 warps, warp tile 32x64. 2 CTAs/SM.
// =======================================================================
template<int MODE>
__global__ __launch_bounds__(256,2) void hgemm(
    const __half* __restrict__ ah,
    int lda, int windowed, int zW0,
    const float* __restrict__ bias0, const float* __restrict__ bias1, int bSplit,
    float* __restrict__ out, int ldo, long long oZ,
    const float* __restrict__ Q,
    const float* __restrict__ R,
    float* __restrict__ partial, int pZ0)
{
  const int z = blockIdx.z;
  const int widx = windowed ? (z + (z>=8 ? 1 : 0)) : 0;
  const __half* Ah = ah + widx*Dd;
  const __half* Wh = g_wh + (size_t)(zW0+z)*WSZ;
  const float* bp = (z < bSplit) ? bias0 + (size_t)z*Dd : bias1 + (size_t)(z-bSplit)*Dd;
  float* outPtr = out ? out + (size_t)widx*Dd + (size_t)z*oZ : nullptr;

  const int tid = threadIdx.x, lane = tid & 31, wid = tid >> 5;
  const int warpM = wid >> 1, warpN = wid & 1;
  const int bBase = blockIdx.x * 128;
  const int nBase = blockIdx.y * 128;

  extern __shared__ char dsm[];
  const uint32_t dynU = (smem_u32(dsm) + 1023u) & ~1023u;
  __shared__ float biasS[128];
  __shared__ float redS[128][2];

  if (tid < 32) ((float4*)biasS)[tid] = ((const float4*)(bp + nBase))[tid];

  float acc[2][8][4];
  #pragma unroll
  for (int m=0;m<2;m++) for (int n=0;n<8;n++) for (int i=0;i<4;i++) acc[m][n][i]=0.f;

  uint32_t aRowOff[2], bRowOff[4];
  #pragma unroll
  for (int i=0;i<2;i++)
    aRowOff[i] = (uint32_t)((warpM*32 + i*16 + (lane&15)) * 128);
  #pragma unroll
  for (int i=0;i<4;i++)
    bRowOff[i] = (uint32_t)((warpN*64 + i*16 + (lane&7) + ((lane&16)>>1)) * 128);
  const int aXb = lane >> 4, bXb = (lane >> 3) & 1, lx = lane & 7;

  // stage: A 128x64 fp16 (16KB) | B 128x64 fp16 (16KB)
  auto loadStage = [&](int s, int buf){
    const int kOff = s * 64;
    const uint32_t base = dynU + buf*STG;
    #pragma unroll
    for (int i=0;i<4;i++){
      int idx = i*256 + tid, row = idx>>3, g = idx&7;
      uint32_t sw = SWZ((uint32_t)(row*128 + g*16));
      CP16(base + sw,         Ah + (size_t)(bBase+row)*(size_t)lda + kOff + g*8);
      CP16(base + 16384 + sw, Wh + (size_t)(nBase+row)*Dd + kOff + g*8);
    }
  };

  loadStage(0, 0); CPCOMMIT();
  loadStage(1, 1); CPCOMMIT();

  for (int s = 0; s < NST; s++){
    CPWAIT1();
    __syncthreads();
    if (s + 2 < NST) loadStage(s+2, (s+2)%3);
    CPCOMMIT();                       // empty group when no load keeps count exact
    const uint32_t aB = dynU + (s%3)*STG;
    const uint32_t bB = aB + 16384;
    #pragma unroll
    for (int q=0;q<4;q++){
      const uint32_t selA = (uint32_t)(((2*q + aXb) ^ lx) << 4);
      const uint32_t selB = (uint32_t)(((2*q + bXb) ^ lx) << 4);
      uint32_t aF[2][4], bF[4][4];
      #pragma unroll
      for (int mt=0;mt<2;mt++) ldsm4(aF[mt], aB + aRowOff[mt] + selA);
      #pragma unroll
      for (int nt=0;nt<4;nt++) ldsm4(bF[nt], bB + bRowOff[nt] + selB);
      #pragma unroll
      for (int mt=0;mt<2;mt++)
        #pragma unroll
        for (int nt=0;nt<4;nt++){
          MMA(acc[mt][nt*2],   aF[mt], bF[nt][0], bF[nt][1]);
          MMA(acc[mt][nt*2+1], aF[mt], bF[nt][2], bF[nt][3]);
        }
    }
  }

  // ---------------- epilogue ----------------
  if constexpr (MODE == M_STORE){
    #pragma unroll
    for (int mt=0;mt<2;mt++){
      const int rl0 = warpM*32 + mt*16 + (lane>>2);
      float* o0 = outPtr + (size_t)(bBase+rl0)*(size_t)ldo;
      float* o1 = o0 + (size_t)8*(size_t)ldo;
      #pragma unroll
      for (int nt=0;nt<8;nt++){
        const int bl = warpN*64 + nt*8 + ((lane&3)<<1);
        const int c  = nBase + bl;
        float bx = biasS[bl], by = biasS[bl+1];
        *(float2*)(o0 + c) = make_float2(acc[mt][nt][0]+bx, acc[mt][nt][1]+by);
        *(float2*)(o1 + c) = make_float2(acc[mt][nt][2]+bx, acc[mt][nt][3]+by);
      }
    }
  }
  else if constexpr (MODE == M_DOT){
    #pragma unroll
    for (int mt=0;mt<2;mt++){
      const int rl0 = warpM*32 + mt*16 + (lane>>2);
      const float* q0 = Q + (size_t)(bBase+rl0)*Dd;
      const float* q1 = q0 + (size_t)8*Dd;
      float s0 = 0.f, s1 = 0.f;
      #pragma unroll
      for (int nt=0;nt<8;nt++){
        const int bl = warpN*64 + nt*8 + ((lane&3)<<1);
        const int c  = nBase + bl;
        float bx = biasS[bl], by = biasS[bl+1];
        float2 qa = *(const float2*)(q0 + c);
        float2 qb = *(const float2*)(q1 + c);
        s0 += (acc[mt][nt][0]+bx)*qa.x + (acc[mt][nt][1]+by)*qa.y;
        s1 += (acc[mt][nt][2]+bx)*qb.x + (acc[mt][nt][3]+by)*qb.y;
      }
      s0 += __shfl_xor_sync(0xffffffffu, s0, 1); s0 += __shfl_xor_sync(0xffffffffu, s0, 2);
      s1 += __shfl_xor_sync(0xffffffffu, s1, 1); s1 += __shfl_xor_sync(0xffffffffu, s1, 2);
      if ((lane&3) == 0){ redS[rl0][warpN] = s0; redS[rl0+8][warpN] = s1; }
    }
    __syncthreads();
    if (tid < 128){
      float p = redS[tid][0] + redS[tid][1];
      partial[((size_t)z*Bsz + bBase + tid)*4 + blockIdx.y] = p;
    }
  }
  else { // M_NORM / M_NORM_RES
    #pragma unroll
    for (int mt=0;mt<2;mt++){
      const int rl0 = warpM*32 + mt*16 + (lane>>2);
      float* o0 = outPtr + (size_t)(bBase+rl0)*(size_t)ldo;
      float* o1 = o0 + (size_t)8*(size_t)ldo;
      const float* r0p = (MODE==M_NORM_RES) ? (R + (size_t)(bBase+rl0)*XS) : nullptr;
      const float* r1p = (MODE==M_NORM_RES) ? (r0p + (size_t)8*XS) : nullptr;
      float s0 = 0.f, s1 = 0.f;
      #pragma unroll
      for (int nt=0;nt<8;nt++){
        const int bl = warpN*64 + nt*8 + ((lane&3)<<1);
        const int c  = nBase + bl;
        float bx = biasS[bl], by = biasS[bl+1];
        float v00 = acc[mt][nt][0]+bx, v01 = acc[mt][nt][1]+by;
        float v10 = acc[mt][nt][2]+bx, v11 = acc[mt][nt][3]+by;
        if constexpr (MODE==M_NORM_RES){
          float2 ra = *(const float2*)(r0p + c);
          float2 rb = *(const float2*)(r1p + c);
          v00 += ra.x; v01 += ra.y; v10 += rb.x; v11 += rb.y;
        }
        *(float2*)(o0 + c) = make_float2(v00, v01);
        *(float2*)(o1 + c) = make_float2(v10, v11);
        s0 += v00*v00 + v01*v01;
        s1 += v10*v10 + v11*v11;
      }
      s0 += __shfl_xor_sync(0xffffffffu, s0, 1); s0 += __shfl_xor_sync(0xffffffffu, s0, 2);
      s1 += __shfl_xor_sync(0xffffffffu, s1, 1); s1 += __shfl_xor_sync(0xffffffffu, s1, 2);
      if ((lane&3) == 0){ redS[rl0][warpN] = s0; redS[rl0+8][warpN] = s1; }
    }
    __syncthreads();
    if (tid < 128){
      float p = redS[tid][0] + redS[tid][1];
      partial[((size_t)(pZ0+z)*Bsz + bBase + tid)*4 + blockIdx.y] = p;
    }
  }
}

// =======================================================================
// second pass: per-row l2 normalization in-place on out, 17 segments
// =======================================================================
__global__ void norm_scale(float* __restrict__ out, const float* __restrict__ partial){
  const int b = blockIdx.x, zi = blockIdx.y, t = threadIdx.x;
  const float* p = partial + ((size_t)zi*Bsz + b)*4;
  float ss = p[0]+p[1]+p[2]+p[3];
  float sc = 1.f / fmaxf(sqrtf(ss), 1e-12f);
  int col0 = (zi==16) ? 4096 : ((zi<8) ? zi*512 : (zi+1)*512);
  float4* row = (float4*)(out + (size_t)b*XS + col0);
  float4 v = row[t];
  v.x*=sc; v.y*=sc; v.z*=sc; v.w*=sc;
  row[t] = v;
}

// =======================================================================
// mix: attn = q.kc; v = l2norm(xc*attn + sum_w ap*xp_w + sum_w an*xn_w)
// =======================================================================
__global__ void mix_kernel(const float* __restrict__ x, float* __restrict__ outv,
                           const float* __restrict__ q, const float* __restrict__ kc,
                           const float* __restrict__ dotP)
{
  __shared__ float sb[4];
  const int b = blockIdx.x, t = threadIdx.x;
  const float4* xr = (const float4*)(x + (size_t)b*XS);

  float4 q4 = ((const float4*)(q  + (size_t)b*Dd))[t];
  float4 k4 = ((const float4*)(kc + (size_t)b*Dd))[t];
  float part = q4.x*k4.x + q4.y*k4.y + q4.z*k4.z + q4.w*k4.w;
  #pragma unroll
  for (int o=16;o;o>>=1) part += __shfl_xor_sync(0xffffffffu, part, o);
  if ((t & 31) == 0) sb[t>>5] = part;
  __syncthreads();
  const float attn = sb[0] + sb[1] + sb[2] + sb[3];
  __syncthreads();

  float4 xc4 = xr[1024 + t];
  float4 acc;
  acc.x = xc4.x*attn; acc.y = xc4.y*attn; acc.z = xc4.z*attn; acc.w = xc4.w*attn;
  #pragma unroll
  for (int w=0;w<8;w++){
    float4 pa = *(const float4*)(dotP + ((size_t)w*Bsz + b)*4);
    float aw = pa.x + pa.y + pa.z + pa.w;
    float4 p4 = xr[w*128 + t];
    acc.x += aw*p4.x; acc.y += aw*p4.y; acc.z += aw*p4.z; acc.w += aw*p4.w;
    float4 pn = *(const float4*)(dotP + ((size_t)(8+w)*Bsz + b)*4);
    float nw = pn.x + pn.y + pn.z + pn.w;
    float4 n4 = xr[(9+w)*128 + t];
    acc.x += nw*n4.x; acc.y += nw*n4.y; acc.z += nw*n4.z; acc.w += nw*n4.w;
  }
  float ss = acc.x*acc.x + acc.y*acc.y + acc.z*acc.z + acc.w*acc.w;
  #pragma unroll
  for (int o=16;o;o>>=1) ss += __shfl_xor_sync(0xffffffffu, ss, o);
  if ((t & 31) == 0) sb[t>>5] = ss;
  __syncthreads();
  float tot = sb[0] + sb[1] + sb[2] + sb[3];
  float sc = 1.f / fmaxf(sqrtf(tot), 1e-12f);
  float4 v; v.x = acc.x*sc; v.y = acc.y*sc; v.z = acc.z*sc; v.w = acc.w*sc;
  ((float4*)(outv + (size_t)b*Dd))[t] = v;
}

// =======================================================================
extern "C" void kernel_launch(void* const* d_in, const int* in_sizes, int n_in,
                              void* d_out, int out_size)
{
  const float* x   = (const float*)d_in[0];
  const float* Wq  = (const float*)d_in[1];
  const float* bq  = (const float*)d_in[2];
  const float* Wkc = (const float*)d_in[3];
  const float* bkc = (const float*)d_in[4];
  const float* Wkp = (const float*)d_in[5];
  const float* bkp = (const float*)d_in[6];
  const float* Wkn = (const float*)d_in[7];
  const float* bkn = (const float*)d_in[8];
  const float* Wfp = (const float*)d_in[9];
  const float* bfp = (const float*)d_in[10];
  const float* Wfn = (const float*)d_in[11];
  const float* bfn = (const float*)d_in[12];
  const float* Wfc = (const float*)d_in[13];
  const float* bfc = (const float*)d_in[14];
  float* out = (float*)d_out;

  __half *xh, *vh, *wh;
  float *qkc, *v, *dotP, *nrmP;
  cudaGetSymbolAddress((void**)&xh, g_xh);
  cudaGetSymbolAddress((void**)&wh, g_wh);
  cudaGetSymbolAddress((void**)&vh, g_vh);
  cudaGetSymbolAddress((void**)&qkc,  s_qkc);
  cudaGetSymbolAddress((void**)&v,    s_v);
  cudaGetSymbolAddress((void**)&dotP, s_dotP);
  cudaGetSymbolAddress((void**)&nrmP, s_nrmP);
  float* q  = qkc;
  float* kc = qkc + (size_t)Bsz*Dd;

  cudaFuncSetAttribute(hgemm<M_STORE>,    cudaFuncAttributeMaxDynamicSharedMemorySize, DYN_SMEM);
  cudaFuncSetAttribute(hgemm<M_DOT>,      cudaFuncAttributeMaxDynamicSharedMemorySize, DYN_SMEM);
  cudaFuncSetAttribute(hgemm<M_NORM>,     cudaFuncAttributeMaxDynamicSharedMemorySize, DYN_SMEM);
  cudaFuncSetAttribute(hgemm<M_NORM_RES>, cudaFuncAttributeMaxDynamicSharedMemorySize, DYN_SMEM);

  // [0] x -> fp16
  { int n8 = (Bsz*XS)/8; cvtH<<<(n8+255)/256, 256>>>(x, xh, n8); }
  // [1] all 35 weights -> fp16, one launch
  cvtW<<<(NW*(WSZ/8))/256, 256>>>(Wq, Wkc, Wkp, Wkn, Wfp, Wfn, Wfc, wh);

  // [2] q / kc
  hgemm<M_STORE><<<dim3(64,4,2), 256, DYN_SMEM>>>(
      xh+4096, XS, 0, 0, bq, bkc, 1,
      qkc, Dd, (long long)Bsz*Dd, nullptr, nullptr, nullptr, 0);

  // [3] ap/an partial dots (kp/kn never materialized)
  hgemm<M_DOT><<<dim3(64,4,16), 256, DYN_SMEM>>>(
      xh, XS, 1, 2, bkp, bkn, 8,
      nullptr, 0, 0, q, nullptr, dotP, 0);

  // [4] mix -> v
  mix_kernel<<<Bsz, 128>>>(x, v, q, kc, dotP);

  // [5] fp/fn raw + sumsq partials, straight into d_out
  hgemm<M_NORM><<<dim3(64,4,16), 256, DYN_SMEM>>>(
      xh, XS, 1, 18, bfp, bfn, 8,
      out, XS, 0, nullptr, nullptr, nrmP, 0);

  // [6] convert v -> fp16
  { int n8 = (Bsz*Dd)/8; cvtH<<<(n8+255)/256, 256>>>(v, vh, n8); }

  // [7] fc (+ residual xc) raw + partials
  hgemm<M_NORM_RES><<<dim3(64,4,1), 256, DYN_SMEM>>>(
      vh, Dd, 0, 34, bfc, bfc, 1,
      out+4096, XS, 0, nullptr, x+4096, nrmP, 16);

  // [8] in-place l2 normalization of all 17 segments
  norm_scale<<<dim3(Bsz,17), 128>>>(out, nrmP);
}

// round 8
// speedup vs baseline: 8.6447x; 1.1718x over previous
#include <cuda_runtime.h>
#include <cuda_fp16.h>
#include <cstdint>

#define Bsz 8192
#define Dd  512
#define XS  8704           // 17*512 row stride of x / out
#define WSZ 262144         // 512*512 per weight matrix
#define NW  35
#define NST 8              // 8 k-chunks of 64
#define STG 32768          // per-stage smem: A 16K + B 16K
#define DYN_SMEM (3*STG + 1024)

enum { M_STORE=0, M_DOT=1, M_NORM=2, M_NORM_RES=3 };

// ---------------- device scratch (allocation-free rule) ----------------
__device__ __align__(256) __half g_xh[Bsz*XS];
__device__ __align__(256) __half g_wh[NW*WSZ];
__device__ __align__(256) __half g_vh[Bsz*Dd];
__device__ __align__(256) float s_qkc[2*Bsz*Dd];     // q then kc
__device__ __align__(256) float s_dotP[16*Bsz*4];    // [z][b][ctaN]

// ---------------- ptx helpers ----------------
__device__ __forceinline__ uint32_t smem_u32(const void* p){
  uint32_t a;
  asm("{ .reg .u64 t; cvta.to.shared.u64 t, %1; cvt.u32.u64 %0, t; }" : "=r"(a) : "l"(p));
  return a;
}
#define CP16(s,g) asm volatile("cp.async.cg.shared.global [%0], [%1], 16;" :: "r"(s), "l"(g))
#define CPCOMMIT() asm volatile("cp.async.commit_group;" ::: "memory")
#define CPWAIT1()  asm volatile("cp.async.wait_group 1;" ::: "memory")
#define CLUSTER_ARRIVE() asm volatile("barrier.cluster.arrive.aligned;" ::: "memory")
#define CLUSTER_WAIT()   asm volatile("barrier.cluster.wait.aligned;" ::: "memory")

__device__ __forceinline__ void ldsm4(uint32_t* r, uint32_t a){
  asm volatile("ldmatrix.sync.aligned.m8n8.x4.shared.b16 {%0,%1,%2,%3}, [%4];"
    : "=r"(r[0]),"=r"(r[1]),"=r"(r[2]),"=r"(r[3]) : "r"(a));
}
#define MMA(c,a,b0,b1) \
  asm volatile("mma.sync.aligned.m16n8k16.row.col.f32.f16.f16.f32 " \
    "{%0,%1,%2,%3},{%4,%5,%6,%7},{%8,%9},{%0,%1,%2,%3};" \
    : "+f"((c)[0]),"+f"((c)[1]),"+f"((c)[2]),"+f"((c)[3]) \
    : "r"((a)[0]),"r"((a)[1]),"r"((a)[2]),"r"((a)[3]),"r"(b0),"r"(b1))

#define SWZ(o) ((o) ^ (((o) >> 3) & 0x70))

// ---------------- fp32 -> fp16 (round-to-nearest) ----------------
__device__ __forceinline__ void cvt8core(const float* __restrict__ s, size_t i,
                                         __half* __restrict__ h){
  float4 a = ((const float4*)s)[2*i], b = ((const float4*)s)[2*i+1];
  __half2 H[4];
  H[0] = __half2(__float2half_rn(a.x), __float2half_rn(a.y));
  H[1] = __half2(__float2half_rn(a.z), __float2half_rn(a.w));
  H[2] = __half2(__float2half_rn(b.x), __float2half_rn(b.y));
  H[3] = __half2(__float2half_rn(b.z), __float2half_rn(b.w));
  ((uint4*)h)[i] = *(uint4*)H;
}

__global__ void cvtH(const float* __restrict__ s, __half* __restrict__ h, int n8){
  int i = blockIdx.x*256 + threadIdx.x;
  if (i >= n8) return;
  cvt8core(s, i, h);
}

// all 35 weight matrices -> fp16, one launch
__global__ void cvtW(const float* __restrict__ Wq,  const float* __restrict__ Wkc,
                     const float* __restrict__ Wkp, const float* __restrict__ Wkn,
                     const float* __restrict__ Wfp, const float* __restrict__ Wfn,
                     const float* __restrict__ Wfc, __half* __restrict__ h){
  const int perW = WSZ/8;
  int i = blockIdx.x*256 + threadIdx.x;
  int w = i / perW, j = i - w*perW;
  const float* src;
  if      (w == 0)  src = Wq;
  else if (w == 1)  src = Wkc;
  else if (w < 10)  src = Wkp + (size_t)(w-2)*WSZ;
  else if (w < 18)  src = Wkn + (size_t)(w-10)*WSZ;
  else if (w < 26)  src = Wfp + (size_t)(w-18)*WSZ;
  else if (w < 34)  src = Wfn + (size_t)(w-26)*WSZ;
  else              src = Wfc;
  cvt8core(src, j, h + (size_t)w*WSZ);
}

// =======================================================================
// HMMA GEMM: CTA tile 128(M) x 128(N), fp16, k-chunk 64, 3-stage cp.async.
// grid = (64, 4, nz), cluster (1,4,1): the 4 N-CTAs of a row block are
// co-scheduled; NORM modes exchange sumsq partials via DSMEM and store
// fully-normalized output directly (no second pass).
// =======================================================================
template<int MODE>
__global__ void __cluster_dims__(1,4,1) __launch_bounds__(256,2) hgemm(
    const __half* __restrict__ ah,
    int lda, int windowed, int zW0,
    const float* __restrict__ bias0, const float* __restrict__ bias1, int bSplit,
    float* __restrict__ out, int ldo, long long oZ,
    const float* __restrict__ Q,
    const float* __restrict__ R,
    float* __restrict__ partial)
{
  const int z = blockIdx.z;
  const int widx = windowed ? (z + (z>=8 ? 1 : 0)) : 0;
  const __half* Ah = ah + widx*Dd;
  const __half* Wh = g_wh + (size_t)(zW0+z)*WSZ;
  const float* bp = (z < bSplit) ? bias0 + (size_t)z*Dd : bias1 + (size_t)(z-bSplit)*Dd;
  float* outPtr = out ? out + (size_t)widx*Dd + (size_t)z*oZ : nullptr;

  const int tid = threadIdx.x, lane = tid & 31, wid = tid >> 5;
  const int warpM = wid >> 1, warpN = wid & 1;
  const int bBase = blockIdx.x * 128;
  const int nBase = blockIdx.y * 128;

  extern __shared__ char dsm[];
  const uint32_t dynU = (smem_u32(dsm) + 1023u) & ~1023u;
  __shared__ float biasS[128];
  __shared__ float redS[128][2];
  __shared__ float normP[128];
  __shared__ float scaleS[128];

  if (tid < 32) ((float4*)biasS)[tid] = ((const float4*)(bp + nBase))[tid];

  float acc[2][8][4];
  #pragma unroll
  for (int m=0;m<2;m++) for (int n=0;n<8;n++) for (int i=0;i<4;i++) acc[m][n][i]=0.f;

  uint32_t aRowOff[2], bRowOff[4];
  #pragma unroll
  for (int i=0;i<2;i++)
    aRowOff[i] = (uint32_t)((warpM*32 + i*16 + (lane&15)) * 128);
  #pragma unroll
  for (int i=0;i<4;i++)
    bRowOff[i] = (uint32_t)((warpN*64 + i*16 + (lane&7) + ((lane&16)>>1)) * 128);
  const int aXb = lane >> 4, bXb = (lane >> 3) & 1, lx = lane & 7;

  auto loadStage = [&](int s, int buf){
    const int kOff = s * 64;
    const uint32_t base = dynU + buf*STG;
    #pragma unroll
    for (int i=0;i<4;i++){
      int idx = i*256 + tid, row = idx>>3, g = idx&7;
      uint32_t sw = SWZ((uint32_t)(row*128 + g*16));
      CP16(base + sw,         Ah + (size_t)(bBase+row)*(size_t)lda + kOff + g*8);
      CP16(base + 16384 + sw, Wh + (size_t)(nBase+row)*Dd + kOff + g*8);
    }
  };

  loadStage(0, 0); CPCOMMIT();
  loadStage(1, 1); CPCOMMIT();

  for (int s = 0; s < NST; s++){
    CPWAIT1();
    __syncthreads();
    if (s + 2 < NST) loadStage(s+2, (s+2)%3);
    CPCOMMIT();
    const uint32_t aB = dynU + (s%3)*STG;
    const uint32_t bB = aB + 16384;
    #pragma unroll
    for (int q=0;q<4;q++){
      const uint32_t selA = (uint32_t)(((2*q + aXb) ^ lx) << 4);
      const uint32_t selB = (uint32_t)(((2*q + bXb) ^ lx) << 4);
      uint32_t aF[2][4], bF[4][4];
      #pragma unroll
      for (int mt=0;mt<2;mt++) ldsm4(aF[mt], aB + aRowOff[mt] + selA);
      #pragma unroll
      for (int nt=0;nt<4;nt++) ldsm4(bF[nt], bB + bRowOff[nt] + selB);
      #pragma unroll
      for (int mt=0;mt<2;mt++)
        #pragma unroll
        for (int nt=0;nt<4;nt++){
          MMA(acc[mt][nt*2],   aF[mt], bF[nt][0], bF[nt][1]);
          MMA(acc[mt][nt*2+1], aF[mt], bF[nt][2], bF[nt][3]);
        }
    }
  }

  // ---------------- epilogue ----------------
  if constexpr (MODE == M_STORE){
    #pragma unroll
    for (int mt=0;mt<2;mt++){
      const int rl0 = warpM*32 + mt*16 + (lane>>2);
      float* o0 = outPtr + (size_t)(bBase+rl0)*(size_t)ldo;
      float* o1 = o0 + (size_t)8*(size_t)ldo;
      #pragma unroll
      for (int nt=0;nt<8;nt++){
        const int bl = warpN*64 + nt*8 + ((lane&3)<<1);
        const int c  = nBase + bl;
        float bx = biasS[bl], by = biasS[bl+1];
        *(float2*)(o0 + c) = make_float2(acc[mt][nt][0]+bx, acc[mt][nt][1]+by);
        *(float2*)(o1 + c) = make_float2(acc[mt][nt][2]+bx, acc[mt][nt][3]+by);
      }
    }
  }
  else if constexpr (MODE == M_DOT){
    #pragma unroll
    for (int mt=0;mt<2;mt++){
      const int rl0 = warpM*32 + mt*16 + (lane>>2);
      const float* q0 = Q + (size_t)(bBase+rl0)*Dd;
      const float* q1 = q0 + (size_t)8*Dd;
      float s0 = 0.f, s1 = 0.f;
      #pragma unroll
      for (int nt=0;nt<8;nt++){
        const int bl = warpN*64 + nt*8 + ((lane&3)<<1);
        const int c  = nBase + bl;
        float bx = biasS[bl], by = biasS[bl+1];
        float2 qa = *(const float2*)(q0 + c);
        float2 qb = *(const float2*)(q1 + c);
        s0 += (acc[mt][nt][0]+bx)*qa.x + (acc[mt][nt][1]+by)*qa.y;
        s1 += (acc[mt][nt][2]+bx)*qb.x + (acc[mt][nt][3]+by)*qb.y;
      }
      s0 += __shfl_xor_sync(0xffffffffu, s0, 1); s0 += __shfl_xor_sync(0xffffffffu, s0, 2);
      s1 += __shfl_xor_sync(0xffffffffu, s1, 1); s1 += __shfl_xor_sync(0xffffffffu, s1, 2);
      if ((lane&3) == 0){ redS[rl0][warpN] = s0; redS[rl0+8][warpN] = s1; }
    }
    __syncthreads();
    if (tid < 128){
      float p = redS[tid][0] + redS[tid][1];
      partial[((size_t)z*Bsz + bBase + tid)*4 + blockIdx.y] = p;
    }
  }
  else { // M_NORM / M_NORM_RES — cluster-fused normalization
    // pass 1: add bias (+R), stash into acc, per-CTA sumsq partials
    #pragma unroll
    for (int mt=0;mt<2;mt++){
      const int rl0 = warpM*32 + mt*16 + (lane>>2);
      const float* r0p = (MODE==M_NORM_RES) ? (R + (size_t)(bBase+rl0)*XS) : nullptr;
      const float* r1p = (MODE==M_NORM_RES) ? (r0p + (size_t)8*XS) : nullptr;
      float s0 = 0.f, s1 = 0.f;
      #pragma unroll
      for (int nt=0;nt<8;nt++){
        const int bl = warpN*64 + nt*8 + ((lane&3)<<1);
        const int c  = nBase + bl;
        float bx = biasS[bl], by = biasS[bl+1];
        float v00 = acc[mt][nt][0]+bx, v01 = acc[mt][nt][1]+by;
        float v10 = acc[mt][nt][2]+bx, v11 = acc[mt][nt][3]+by;
        if constexpr (MODE==M_NORM_RES){
          float2 ra = *(const float2*)(r0p + c);
          float2 rb = *(const float2*)(r1p + c);
          v00 += ra.x; v01 += ra.y; v10 += rb.x; v11 += rb.y;
        }
        acc[mt][nt][0]=v00; acc[mt][nt][1]=v01;
        acc[mt][nt][2]=v10; acc[mt][nt][3]=v11;
        s0 += v00*v00 + v01*v01;
        s1 += v10*v10 + v11*v11;
      }
      s0 += __shfl_xor_sync(0xffffffffu, s0, 1); s0 += __shfl_xor_sync(0xffffffffu, s0, 2);
      s1 += __shfl_xor_sync(0xffffffffu, s1, 1); s1 += __shfl_xor_sync(0xffffffffu, s1, 2);
      if ((lane&3) == 0){ redS[rl0][warpN] = s0; redS[rl0+8][warpN] = s1; }
    }
    __syncthreads();
    if (tid < 128) normP[tid] = redS[tid][0] + redS[tid][1];
    // DSMEM exchange across the 4 N-CTAs of this cluster
    CLUSTER_ARRIVE(); CLUSTER_WAIT();
    if (tid < 128){
      const uint32_t loc = smem_u32(normP) + (uint32_t)tid*4;
      float tot = 0.f;
      #pragma unroll
      for (int r=0;r<4;r++){
        uint32_t rem; float pv;
        asm volatile("mapa.shared::cluster.u32 %0, %1, %2;" : "=r"(rem) : "r"(loc), "r"(r));
        asm volatile("ld.shared::cluster.f32 %0, [%1];" : "=f"(pv) : "r"(rem));
        tot += pv;
      }
      scaleS[tid] = 1.f / fmaxf(sqrtf(tot), 1e-12f);
    }
    CLUSTER_ARRIVE(); CLUSTER_WAIT();   // all reads done before any CTA proceeds/exits
    __syncthreads();
    // pass 2: rescale and store normalized
    #pragma unroll
    for (int mt=0;mt<2;mt++){
      const int rl0 = warpM*32 + mt*16 + (lane>>2);
      const float sc0 = scaleS[rl0], sc1 = scaleS[rl0+8];
      float* o0 = outPtr + (size_t)(bBase+rl0)*(size_t)ldo;
      float* o1 = o0 + (size_t)8*(size_t)ldo;
      #pragma unroll
      for (int nt=0;nt<8;nt++){
        const int c = nBase + warpN*64 + nt*8 + ((lane&3)<<1);
        *(float2*)(o0 + c) = make_float2(acc[mt][nt][0]*sc0, acc[mt][nt][1]*sc0);
        *(float2*)(o1 + c) = make_float2(acc[mt][nt][2]*sc1, acc[mt][nt][3]*sc1);
      }
    }
  }
}

// =======================================================================
// mix: attn = q.kc; v = l2norm(xc*attn + sum_w ap*xp_w + sum_w an*xn_w)
// windows read from fp16 xh; center xc from fp32 x; writes fp16 vh only.
// =======================================================================
__global__ void mix_kernel(const float* __restrict__ x, __half* __restrict__ outvh,
                           const float* __restrict__ q, const float* __restrict__ kc,
                           const float* __restrict__ dotP)
{
  __shared__ float sb[4];
  const int b = blockIdx.x, t = threadIdx.x;
  const __half* xhr = g_xh + (size_t)b*XS;

  float4 q4 = ((const float4*)(q  + (size_t)b*Dd))[t];
  float4 k4 = ((const float4*)(kc + (size_t)b*Dd))[t];
  float part = q4.x*k4.x + q4.y*k4.y + q4.z*k4.z + q4.w*k4.w;
  #pragma unroll
  for (int o=16;o;o>>=1) part += __shfl_xor_sync(0xffffffffu, part, o);
  if ((t & 31) == 0) sb[t>>5] = part;
  __syncthreads();
  const float attn = sb[0] + sb[1] + sb[2] + sb[3];
  __syncthreads();

  float4 xc4 = ((const float4*)(x + (size_t)b*XS + 4096))[t];
  float4 acc;
  acc.x = xc4.x*attn; acc.y = xc4.y*attn; acc.z = xc4.z*attn; acc.w = xc4.w*attn;
  #pragma unroll
  for (int w=0;w<8;w++){
    float4 pa = *(const float4*)(dotP + ((size_t)w*Bsz + b)*4);
    float aw = pa.x + pa.y + pa.z + pa.w;
    uint2 up = *(const uint2*)(xhr + w*512 + t*4);
    float2 p0 = __half22float2(*(__half2*)&up.x);
    float2 p1 = __half22float2(*(__half2*)&up.y);
    acc.x += aw*p0.x; acc.y += aw*p0.y; acc.z += aw*p1.x; acc.w += aw*p1.y;
    float4 pn = *(const float4*)(dotP + ((size_t)(8+w)*Bsz + b)*4);
    float nw = pn.x + pn.y + pn.z + pn.w;
    uint2 un = *(const uint2*)(xhr + (9+w)*512 + t*4);
    float2 n0 = __half22float2(*(__half2*)&un.x);
    float2 n1 = __half22float2(*(__half2*)&un.y);
    acc.x += nw*n0.x; acc.y += nw*n0.y; acc.z += nw*n1.x; acc.w += nw*n1.y;
  }
  float ss = acc.x*acc.x + acc.y*acc.y + acc.z*acc.z + acc.w*acc.w;
  #pragma unroll
  for (int o=16;o;o>>=1) ss += __shfl_xor_sync(0xffffffffu, ss, o);
  if ((t & 31) == 0) sb[t>>5] = ss;
  __syncthreads();
  float tot = sb[0] + sb[1] + sb[2] + sb[3];
  float sc = 1.f / fmaxf(sqrtf(tot), 1e-12f);
  __half2 h0 = __floats2half2_rn(acc.x*sc, acc.y*sc);
  __half2 h1 = __floats2half2_rn(acc.z*sc, acc.w*sc);
  uint2 o; o.x = *(uint32_t*)&h0; o.y = *(uint32_t*)&h1;
  *(uint2*)(outvh + (size_t)b*Dd + t*4) = o;
}

// =======================================================================
extern "C" void kernel_launch(void* const* d_in, const int* in_sizes, int n_in,
                              void* d_out, int out_size)
{
  const float* x   = (const float*)d_in[0];
  const float* Wq  = (const float*)d_in[1];
  const float* bq  = (const float*)d_in[2];
  const float* Wkc = (const float*)d_in[3];
  const float* bkc = (const float*)d_in[4];
  const float* Wkp = (const float*)d_in[5];
  const float* bkp = (const float*)d_in[6];
  const float* Wkn = (const float*)d_in[7];
  const float* bkn = (const float*)d_in[8];
  const float* Wfp = (const float*)d_in[9];
  const float* bfp = (const float*)d_in[10];
  const float* Wfn = (const float*)d_in[11];
  const float* bfn = (const float*)d_in[12];
  const float* Wfc = (const float*)d_in[13];
  const float* bfc = (const float*)d_in[14];
  float* out = (float*)d_out;

  __half *xh, *vh, *wh;
  float *qkc, *dotP;
  cudaGetSymbolAddress((void**)&xh, g_xh);
  cudaGetSymbolAddress((void**)&wh, g_wh);
  cudaGetSymbolAddress((void**)&vh, g_vh);
  cudaGetSymbolAddress((void**)&qkc,  s_qkc);
  cudaGetSymbolAddress((void**)&dotP, s_dotP);
  float* q  = qkc;
  float* kc = qkc + (size_t)Bsz*Dd;

  cudaFuncSetAttribute(hgemm<M_STORE>,    cudaFuncAttributeMaxDynamicSharedMemorySize, DYN_SMEM);
  cudaFuncSetAttribute(hgemm<M_DOT>,      cudaFuncAttributeMaxDynamicSharedMemorySize, DYN_SMEM);
  cudaFuncSetAttribute(hgemm<M_NORM>,     cudaFuncAttributeMaxDynamicSharedMemorySize, DYN_SMEM);
  cudaFuncSetAttribute(hgemm<M_NORM_RES>, cudaFuncAttributeMaxDynamicSharedMemorySize, DYN_SMEM);

  // [0] x -> fp16
  { int n8 = (Bsz*XS)/8; cvtH<<<(n8+255)/256, 256>>>(x, xh, n8); }
  // [1] all 35 weights -> fp16, one launch
  cvtW<<<(NW*(WSZ/8))/256, 256>>>(Wq, Wkc, Wkp, Wkn, Wfp, Wfn, Wfc, wh);

  // [2] q / kc
  hgemm<M_STORE><<<dim3(64,4,2), 256, DYN_SMEM>>>(
      xh+4096, XS, 0, 0, bq, bkc, 1,
      qkc, Dd, (long long)Bsz*Dd, nullptr, nullptr, nullptr);

  // [3] ap/an partial dots (kp/kn never materialized)
  hgemm<M_DOT><<<dim3(64,4,16), 256, DYN_SMEM>>>(
      xh, XS, 1, 2, bkp, bkn, 8,
      nullptr, 0, 0, q, nullptr, dotP);

  // [4] mix -> vh (fp16 direct)
  mix_kernel<<<Bsz, 128>>>(x, vh, q, kc, dotP);

  // [5] fp/fn: fused cluster normalization, straight into d_out
  hgemm<M_NORM><<<dim3(64,4,16), 256, DYN_SMEM>>>(
      xh, XS, 1, 18, bfp, bfn, 8,
      out, XS, 0, nullptr, nullptr, nullptr);

  // [6] fc (+ residual xc), fused cluster normalization
  hgemm<M_NORM_RES><<<dim3(64,4,1), 256, DYN_SMEM>>>(
      vh, Dd, 0, 34, bfc, bfc, 1,
      out+4096, XS, 0, nullptr, x+4096, nullptr);
}

// round 9
// speedup vs baseline: 9.5496x; 1.1047x over previous
#include <cuda_runtime.h>
#include <cuda_fp16.h>
#include <cstdint>

#define Bsz 8192
#define Dd  512
#define XS  8704           // 17*512 row stride of x / out
#define WSZ 262144         // 512*512 per weight matrix
#define NW  35
#define NST 8              // 8 k-chunks of 64
#define STG 32768          // per-stage smem: A 16K + B 16K
#define DYN_SMEM (3*STG + 1024)

// ---------------- device scratch (allocation-free rule) ----------------
__device__ __align__(256) __half g_xh[Bsz*XS];
__device__ __align__(256) __half g_wh[NW*WSZ];
__device__ __align__(256) __half g_vh[Bsz*Dd];
__device__ __align__(256) float s_qkc[2*Bsz*Dd];     // q then kc
__device__ __align__(256) float s_dotP[16*Bsz*4];    // [z][b][ctaN]

// ---------------- ptx helpers ----------------
__device__ __forceinline__ uint32_t smem_u32(const void* p){
  uint32_t a;
  asm("{ .reg .u64 t; cvta.to.shared.u64 t, %1; cvt.u32.u64 %0, t; }" : "=r"(a) : "l"(p));
  return a;
}
#define CP16(s,g) asm volatile("cp.async.cg.shared.global [%0], [%1], 16;" :: "r"(s), "l"(g))
#define CPCOMMIT() asm volatile("cp.async.commit_group;" ::: "memory")
#define CPWAIT1()  asm volatile("cp.async.wait_group 1;" ::: "memory")
#define CLUSTER_ARRIVE() asm volatile("barrier.cluster.arrive.aligned;" ::: "memory")
#define CLUSTER_WAIT()   asm volatile("barrier.cluster.wait.aligned;" ::: "memory")

__device__ __forceinline__ void ldsm4(uint32_t* r, uint32_t a){
  asm volatile("ldmatrix.sync.aligned.m8n8.x4.shared.b16 {%0,%1,%2,%3}, [%4];"
    : "=r"(r[0]),"=r"(r[1]),"=r"(r[2]),"=r"(r[3]) : "r"(a));
}
#define MMA(c,a,b0,b1) \
  asm volatile("mma.sync.aligned.m16n8k16.row.col.f32.f16.f16.f32 " \
    "{%0,%1,%2,%3},{%4,%5,%6,%7},{%8,%9},{%0,%1,%2,%3};" \
    : "+f"((c)[0]),"+f"((c)[1]),"+f"((c)[2]),"+f"((c)[3]) \
    : "r"((a)[0]),"r"((a)[1]),"r"((a)[2]),"r"((a)[3]),"r"(b0),"r"(b1))

#define SWZ(o) ((o) ^ (((o) >> 3) & 0x70))

// ---------------- fp32 -> fp16 (round-to-nearest) ----------------
__device__ __forceinline__ void cvt8core(const float* __restrict__ s, size_t i,
                                         __half* __restrict__ h){
  float4 a = ((const float4*)s)[2*i], b = ((const float4*)s)[2*i+1];
  __half2 H[4];
  H[0] = __half2(__float2half_rn(a.x), __float2half_rn(a.y));
  H[1] = __half2(__float2half_rn(a.z), __float2half_rn(a.w));
  H[2] = __half2(__float2half_rn(b.x), __float2half_rn(b.y));
  H[3] = __half2(__float2half_rn(b.z), __float2half_rn(b.w));
  ((uint4*)h)[i] = *(uint4*)H;
}

// x AND all 35 weights in one launch
__global__ void cvtAll(const float* __restrict__ x,
                       const float* __restrict__ Wq,  const float* __restrict__ Wkc,
                       const float* __restrict__ Wkp, const float* __restrict__ Wkn,
                       const float* __restrict__ Wfp, const float* __restrict__ Wfn,
                       const float* __restrict__ Wfc){
  const int xB = (Bsz*XS/8)/256;   // 34816 blocks for x
  const int bid = blockIdx.x;
  if (bid < xB){
    int i = bid*256 + threadIdx.x;
    cvt8core(x, i, g_xh);
  } else {
    int i = (bid - xB)*256 + threadIdx.x;
    int w = i >> 15;               // / 32768 items per weight matrix
    int j = i & 32767;
    const float* src;
    if      (w == 0)  src = Wq;
    else if (w == 1)  src = Wkc;
    else if (w < 10)  src = Wkp + (size_t)(w-2)*WSZ;
    else if (w < 18)  src = Wkn + (size_t)(w-10)*WSZ;
    else if (w < 26)  src = Wfp + (size_t)(w-18)*WSZ;
    else if (w < 34)  src = Wfn + (size_t)(w-26)*WSZ;
    else              src = Wfc;
    cvt8core(src, j, g_wh + (size_t)w*WSZ);
  }
}

// =======================================================================
// Shared mainloop: CTA tile 128x128, fp16, k-chunk 64, 3-stage cp.async,
// register-level fragment double buffering (A 2-buf, B two half-buffers).
// =======================================================================
__device__ __forceinline__ void gemm_mainloop(
    const __half* __restrict__ Ah, int lda,
    const __half* __restrict__ Wh,
    int bBase, int nBase, uint32_t dynU,
    float (&acc)[2][8][4])
{
  const int tid = threadIdx.x, lane = tid & 31, wid = tid >> 5;
  const int warpM = wid >> 1, warpN = wid & 1;

  uint32_t aRowOff[2], bRowOff[4];
  #pragma unroll
  for (int i=0;i<2;i++)
    aRowOff[i] = (uint32_t)((warpM*32 + i*16 + (lane&15)) * 128);
  #pragma unroll
  for (int i=0;i<4;i++)
    bRowOff[i] = (uint32_t)((warpN*64 + i*16 + (lane&7) + ((lane&16)>>1)) * 128);
  const int aXb = lane >> 4, bXb = (lane >> 3) & 1, lx = lane & 7;
  uint32_t selA[4], selB[4];
  #pragma unroll
  for (int q=0;q<4;q++){
    selA[q] = (uint32_t)(((2*q + aXb) ^ lx) << 4);
    selB[q] = (uint32_t)(((2*q + bXb) ^ lx) << 4);
  }

  auto loadStage = [&](int s, int buf){
    const int kOff = s * 64;
    const uint32_t base = dynU + buf*STG;
    #pragma unroll
    for (int i=0;i<4;i++){
      int idx = i*256 + tid, row = idx>>3, g = idx&7;
      uint32_t sw = SWZ((uint32_t)(row*128 + g*16));
      CP16(base + sw,         Ah + (size_t)(bBase+row)*(size_t)lda + kOff + g*8);
      CP16(base + 16384 + sw, Wh + (size_t)(nBase+row)*Dd + kOff + g*8);
    }
  };

  loadStage(0, 0); CPCOMMIT();
  loadStage(1, 1); CPCOMMIT();

  uint32_t aF[2][2][4], bH[2][2][4];

  #pragma unroll
  for (int s = 0; s < NST; s++){
    CPWAIT1();
    __syncthreads();
    if (s + 2 < NST) loadStage(s+2, (s+2)%3);
    CPCOMMIT();
    const uint32_t aB = dynU + (s%3)*STG;      // compile-time offsets (unrolled)
    const uint32_t bB = aB + 16384;

    // preamble: q0 A frags + first B half
    ldsm4(aF[0][0], aB + aRowOff[0] + selA[0]);
    ldsm4(aF[0][1], aB + aRowOff[1] + selA[0]);
    ldsm4(bH[0][0], bB + bRowOff[0] + selB[0]);
    ldsm4(bH[0][1], bB + bRowOff[1] + selB[0]);

    #pragma unroll
    for (int q=0;q<4;q++){
      const int cur = q&1, nxt = cur^1;
      // prefetch second B half for this q
      ldsm4(bH[1][0], bB + bRowOff[2] + selB[q]);
      ldsm4(bH[1][1], bB + bRowOff[3] + selB[q]);
      // MMA first half (n-tiles 0..3)
      #pragma unroll
      for (int mt=0;mt<2;mt++)
        #pragma unroll
        for (int nt=0;nt<2;nt++){
          MMA(acc[mt][nt*2],   aF[cur][mt], bH[0][nt][0], bH[0][nt][1]);
          MMA(acc[mt][nt*2+1], aF[cur][mt], bH[0][nt][2], bH[0][nt][3]);
        }
      // prefetch next q's A frags + first B half
      if (q < 3){
        ldsm4(aF[nxt][0], aB + aRowOff[0] + selA[q+1]);
        ldsm4(aF[nxt][1], aB + aRowOff[1] + selA[q+1]);
        ldsm4(bH[0][0], bB + bRowOff[0] + selB[q+1]);
        ldsm4(bH[0][1], bB + bRowOff[1] + selB[q+1]);
      }
      // MMA second half (n-tiles 4..7)
      #pragma unroll
      for (int mt=0;mt<2;mt++)
        #pragma unroll
        for (int nt=0;nt<2;nt++){
          MMA(acc[mt][4+nt*2],   aF[cur][mt], bH[1][nt][0], bH[1][nt][1]);
          MMA(acc[mt][4+nt*2+1], aF[cur][mt], bH[1][nt][2], bH[1][nt][3]);
        }
    }
  }
}

// NORM epilogue (cluster-fused l2 normalization), RES adds residual R
template<bool RES>
__device__ __forceinline__ void norm_epilogue(
    float (&acc)[2][8][4], const float* biasS,
    float (*redS)[2], float* normP, float* scaleS,
    float* outPtr, int ldo, const float* R, int ldr,
    int bBase, int nBase)
{
  const int tid = threadIdx.x, lane = tid & 31, wid = tid >> 5;
  const int warpM = wid >> 1, warpN = wid & 1;
  #pragma unroll
  for (int mt=0;mt<2;mt++){
    const int rl0 = warpM*32 + mt*16 + (lane>>2);
    const float* r0p = RES ? (R + (size_t)(bBase+rl0)*(size_t)ldr) : nullptr;
    const float* r1p = RES ? (r0p + (size_t)8*(size_t)ldr) : nullptr;
    float s0 = 0.f, s1 = 0.f;
    #pragma unroll
    for (int nt=0;nt<8;nt++){
      const int bl = warpN*64 + nt*8 + ((lane&3)<<1);
      const int c  = nBase + bl;
      float bx = biasS[bl], by = biasS[bl+1];
      float v00 = acc[mt][nt][0]+bx, v01 = acc[mt][nt][1]+by;
      float v10 = acc[mt][nt][2]+bx, v11 = acc[mt][nt][3]+by;
      if (RES){
        float2 ra = *(const float2*)(r0p + c);
        float2 rb = *(const float2*)(r1p + c);
        v00 += ra.x; v01 += ra.y; v10 += rb.x; v11 += rb.y;
      }
      acc[mt][nt][0]=v00; acc[mt][nt][1]=v01;
      acc[mt][nt][2]=v10; acc[mt][nt][3]=v11;
      s0 += v00*v00 + v01*v01;
      s1 += v10*v10 + v11*v11;
    }
    s0 += __shfl_xor_sync(0xffffffffu, s0, 1); s0 += __shfl_xor_sync(0xffffffffu, s0, 2);
    s1 += __shfl_xor_sync(0xffffffffu, s1, 1); s1 += __shfl_xor_sync(0xffffffffu, s1, 2);
    if ((lane&3) == 0){ redS[rl0][warpN] = s0; redS[rl0+8][warpN] = s1; }
  }
  __syncthreads();
  if (tid < 128) normP[tid] = redS[tid][0] + redS[tid][1];
  CLUSTER_ARRIVE(); CLUSTER_WAIT();
  if (tid < 128){
    const uint32_t loc = smem_u32(normP) + (uint32_t)tid*4;
    float tot = 0.f;
    #pragma unroll
    for (int r=0;r<4;r++){
      uint32_t rem; float pv;
      asm volatile("mapa.shared::cluster.u32 %0, %1, %2;" : "=r"(rem) : "r"(loc), "r"(r));
      asm volatile("ld.shared::cluster.f32 %0, [%1];" : "=f"(pv) : "r"(rem));
      tot += pv;
    }
    scaleS[tid] = 1.f / fmaxf(sqrtf(tot), 1e-12f);
  }
  CLUSTER_ARRIVE(); CLUSTER_WAIT();
  __syncthreads();
  #pragma unroll
  for (int mt=0;mt<2;mt++){
    const int rl0 = warpM*32 + mt*16 + (lane>>2);
    const float sc0 = scaleS[rl0], sc1 = scaleS[rl0+8];
    float* o0 = outPtr + (size_t)(bBase+rl0)*(size_t)ldo;
    float* o1 = o0 + (size_t)8*(size_t)ldo;
    #pragma unroll
    for (int nt=0;nt<8;nt++){
      const int c = nBase + warpN*64 + nt*8 + ((lane&3)<<1);
      *(float2*)(o0 + c) = make_float2(acc[mt][nt][0]*sc0, acc[mt][nt][1]*sc0);
      *(float2*)(o1 + c) = make_float2(acc[mt][nt][2]*sc1, acc[mt][nt][3]*sc1);
    }
  }
}

// =======================================================================
// q/kc GEMM (STORE epilogue), grid (64,4,2)
// =======================================================================
__global__ void __launch_bounds__(256,2) hgemm_store(
    const float* __restrict__ bq, const float* __restrict__ bkc,
    float* __restrict__ qkc)
{
  const int z = blockIdx.z;
  const __half* Ah = g_xh + 4096;
  const __half* Wh = g_wh + (size_t)z*WSZ;
  const float* bp = (z == 0) ? bq : bkc;
  float* outPtr = qkc + (size_t)z*Bsz*Dd;

  const int tid = threadIdx.x, lane = tid & 31, wid = tid >> 5;
  const int warpM = wid >> 1, warpN = wid & 1;
  const int bBase = blockIdx.x * 128, nBase = blockIdx.y * 128;

  extern __shared__ char dsm[];
  const uint32_t dynU = (smem_u32(dsm) + 1023u) & ~1023u;
  __shared__ float biasS[128];
  if (tid < 32) ((float4*)biasS)[tid] = ((const float4*)(bp + nBase))[tid];

  float acc[2][8][4];
  #pragma unroll
  for (int m=0;m<2;m++) for (int n=0;n<8;n++) for (int i=0;i<4;i++) acc[m][n][i]=0.f;

  gemm_mainloop(Ah, XS, Wh, bBase, nBase, dynU, acc);

  #pragma unroll
  for (int mt=0;mt<2;mt++){
    const int rl0 = warpM*32 + mt*16 + (lane>>2);
    float* o0 = outPtr + (size_t)(bBase+rl0)*Dd;
    float* o1 = o0 + (size_t)8*Dd;
    #pragma unroll
    for (int nt=0;nt<8;nt++){
      const int bl = warpN*64 + nt*8 + ((lane&3)<<1);
      const int c  = nBase + bl;
      float bx = biasS[bl], by = biasS[bl+1];
      *(float2*)(o0 + c) = make_float2(acc[mt][nt][0]+bx, acc[mt][nt][1]+by);
      *(float2*)(o1 + c) = make_float2(acc[mt][nt][2]+bx, acc[mt][nt][3]+by);
    }
  }
}

// =======================================================================
// merged DOT (z 0..15: ap/an) + NORM (z 16..31: fp/fn) launch, cluster (1,4,1)
// =======================================================================
__global__ void __cluster_dims__(1,4,1) __launch_bounds__(256,2) hgemm_dn(
    const float* __restrict__ bkp, const float* __restrict__ bkn,
    const float* __restrict__ bfp, const float* __restrict__ bfn,
    const float* __restrict__ Q, float* __restrict__ dotP,
    float* __restrict__ out)
{
  const int z = blockIdx.z;
  const bool isDot = (z < 16);
  const int zw = isDot ? z : z - 16;                 // 0..15 window slot
  const int widx = zw + (zw >= 8 ? 1 : 0);           // skip center
  const __half* Ah = g_xh + widx*Dd;
  const __half* Wh = g_wh + (size_t)((isDot ? 2 : 18) + zw)*WSZ;
  const float* bp = isDot ? ((zw < 8) ? bkp + (size_t)zw*Dd : bkn + (size_t)(zw-8)*Dd)
                          : ((zw < 8) ? bfp + (size_t)zw*Dd : bfn + (size_t)(zw-8)*Dd);

  const int tid = threadIdx.x, lane = tid & 31, wid = tid >> 5;
  const int warpM = wid >> 1, warpN = wid & 1;
  const int bBase = blockIdx.x * 128, nBase = blockIdx.y * 128;

  extern __shared__ char dsm[];
  const uint32_t dynU = (smem_u32(dsm) + 1023u) & ~1023u;
  __shared__ float biasS[128];
  __shared__ float redS[128][2];
  __shared__ float normP[128];
  __shared__ float scaleS[128];
  if (tid < 32) ((float4*)biasS)[tid] = ((const float4*)(bp + nBase))[tid];

  float acc[2][8][4];
  #pragma unroll
  for (int m=0;m<2;m++) for (int n=0;n<8;n++) for (int i=0;i<4;i++) acc[m][n][i]=0.f;

  gemm_mainloop(Ah, XS, Wh, bBase, nBase, dynU, acc);

  if (isDot){
    #pragma unroll
    for (int mt=0;mt<2;mt++){
      const int rl0 = warpM*32 + mt*16 + (lane>>2);
      const float* q0 = Q + (size_t)(bBase+rl0)*Dd;
      const float* q1 = q0 + (size_t)8*Dd;
      float s0 = 0.f, s1 = 0.f;
      #pragma unroll
      for (int nt=0;nt<8;nt++){
        const int bl = warpN*64 + nt*8 + ((lane&3)<<1);
        const int c  = nBase + bl;
        float bx = biasS[bl], by = biasS[bl+1];
        float2 qa = *(const float2*)(q0 + c);
        float2 qb = *(const float2*)(q1 + c);
        s0 += (acc[mt][nt][0]+bx)*qa.x + (acc[mt][nt][1]+by)*qa.y;
        s1 += (acc[mt][nt][2]+bx)*qb.x + (acc[mt][nt][3]+by)*qb.y;
      }
      s0 += __shfl_xor_sync(0xffffffffu, s0, 1); s0 += __shfl_xor_sync(0xffffffffu, s0, 2);
      s1 += __shfl_xor_sync(0xffffffffu, s1, 1); s1 += __shfl_xor_sync(0xffffffffu, s1, 2);
      if ((lane&3) == 0){ redS[rl0][warpN] = s0; redS[rl0+8][warpN] = s1; }
    }
    __syncthreads();
    if (tid < 128){
      float p = redS[tid][0] + redS[tid][1];
      dotP[((size_t)z*Bsz + bBase + tid)*4 + blockIdx.y] = p;
    }
  } else {
    norm_epilogue<false>(acc, biasS, redS, normP, scaleS,
                         out + (size_t)widx*Dd, XS, nullptr, 0, bBase, nBase);
  }
}

// =======================================================================
// fc GEMM (+residual xc, cluster-fused norm), grid (64,4,1)
// =======================================================================
__global__ void __cluster_dims__(1,4,1) __launch_bounds__(256,2) hgemm_fc(
    const float* __restrict__ bfc, const float* __restrict__ x,
    float* __restrict__ out)
{
  const int tid = threadIdx.x;
  const int bBase = blockIdx.x * 128, nBase = blockIdx.y * 128;

  extern __shared__ char dsm[];
  const uint32_t dynU = (smem_u32(dsm) + 1023u) & ~1023u;
  __shared__ float biasS[128];
  __shared__ float redS[128][2];
  __shared__ float normP[128];
  __shared__ float scaleS[128];
  if (tid < 32) ((float4*)biasS)[tid] = ((const float4*)(bfc + nBase))[tid];

  float acc[2][8][4];
  #pragma unroll
  for (int m=0;m<2;m++) for (int n=0;n<8;n++) for (int i=0;i<4;i++) acc[m][n][i]=0.f;

  gemm_mainloop(g_vh, Dd, g_wh + (size_t)34*WSZ, bBase, nBase, dynU, acc);

  norm_epilogue<true>(acc, biasS, redS, normP, scaleS,
                      out + 4096, XS, x + 4096, XS, bBase, nBase);
}

// =======================================================================
// mix: attn = q.kc; vh = fp16(l2norm(xc*attn + sum_w ap*xp_w + an*xn_w))
// =======================================================================
__global__ void mix_kernel(const float* __restrict__ x, __half* __restrict__ outvh,
                           const float* __restrict__ q, const float* __restrict__ kc,
                           const float* __restrict__ dotP)
{
  __shared__ float sb[4];
  const int b = blockIdx.x, t = threadIdx.x;
  const __half* xhr = g_xh + (size_t)b*XS;

  float4 q4 = ((const float4*)(q  + (size_t)b*Dd))[t];
  float4 k4 = ((const float4*)(kc + (size_t)b*Dd))[t];
  float part = q4.x*k4.x + q4.y*k4.y + q4.z*k4.z + q4.w*k4.w;
  #pragma unroll
  for (int o=16;o;o>>=1) part += __shfl_xor_sync(0xffffffffu, part, o);
  if ((t & 31) == 0) sb[t>>5] = part;
  __syncthreads();
  const float attn = sb[0] + sb[1] + sb[2] + sb[3];
  __syncthreads();

  float4 xc4 = ((const float4*)(x + (size_t)b*XS + 4096))[t];
  float4 acc;
  acc.x = xc4.x*attn; acc.y = xc4.y*attn; acc.z = xc4.z*attn; acc.w = xc4.w*attn;
  #pragma unroll
  for (int w=0;w<8;w++){
    float4 pa = *(const float4*)(dotP + ((size_t)w*Bsz + b)*4);
    float aw = pa.x + pa.y + pa.z + pa.w;
    uint2 up = *(const uint2*)(xhr + w*512 + t*4);
    float2 p0 = __half22float2(*(__half2*)&up.x);
    float2 p1 = __half22float2(*(__half2*)&up.y);
    acc.x += aw*p0.x; acc.y += aw*p0.y; acc.z += aw*p1.x; acc.w += aw*p1.y;
    float4 pn = *(const float4*)(dotP + ((size_t)(8+w)*Bsz + b)*4);
    float nw = pn.x + pn.y + pn.z + pn.w;
    uint2 un = *(const uint2*)(xhr + (9+w)*512 + t*4);
    float2 n0 = __half22float2(*(__half2*)&un.x);
    float2 n1 = __half22float2(*(__half2*)&un.y);
    acc.x += nw*n0.x; acc.y += nw*n0.y; acc.z += nw*n1.x; acc.w += nw*n1.y;
  }
  float ss = acc.x*acc.x + acc.y*acc.y + acc.z*acc.z + acc.w*acc.w;
  #pragma unroll
  for (int o=16;o;o>>=1) ss += __shfl_xor_sync(0xffffffffu, ss, o);
  if ((t & 31) == 0) sb[t>>5] = ss;
  __syncthreads();
  float tot = sb[0] + sb[1] + sb[2] + sb[3];
  float sc = 1.f / fmaxf(sqrtf(tot), 1e-12f);
  __half2 h0 = __floats2half2_rn(acc.x*sc, acc.y*sc);
  __half2 h1 = __floats2half2_rn(acc.z*sc, acc.w*sc);
  uint2 o; o.x = *(uint32_t*)&h0; o.y = *(uint32_t*)&h1;
  *(uint2*)(outvh + (size_t)b*Dd + t*4) = o;
}

// =======================================================================
extern "C" void kernel_launch(void* const* d_in, const int* in_sizes, int n_in,
                              void* d_out, int out_size)
{
  const float* x   = (const float*)d_in[0];
  const float* Wq  = (const float*)d_in[1];
  const float* bq  = (const float*)d_in[2];
  const float* Wkc = (const float*)d_in[3];
  const float* bkc = (const float*)d_in[4];
  const float* Wkp = (const float*)d_in[5];
  const float* bkp = (const float*)d_in[6];
  const float* Wkn = (const float*)d_in[7];
  const float* bkn = (const float*)d_in[8];
  const float* Wfp = (const float*)d_in[9];
  const float* bfp = (const float*)d_in[10];
  const float* Wfn = (const float*)d_in[11];
  const float* bfn = (const float*)d_in[12];
  const float* Wfc = (const float*)d_in[13];
  const float* bfc = (const float*)d_in[14];
  float* out = (float*)d_out;

  __half *vh;
  float *qkc, *dotP;
  cudaGetSymbolAddress((void**)&vh,   g_vh);
  cudaGetSymbolAddress((void**)&qkc,  s_qkc);
  cudaGetSymbolAddress((void**)&dotP, s_dotP);
  float* q  = qkc;
  float* kc = qkc + (size_t)Bsz*Dd;

  cudaFuncSetAttribute(hgemm_store, cudaFuncAttributeMaxDynamicSharedMemorySize, DYN_SMEM);
  cudaFuncSetAttribute(hgemm_dn,    cudaFuncAttributeMaxDynamicSharedMemorySize, DYN_SMEM);
  cudaFuncSetAttribute(hgemm_fc,    cudaFuncAttributeMaxDynamicSharedMemorySize, DYN_SMEM);

  // [0] x + all 35 weights -> fp16, one launch
  const int xBlocks = (Bsz*XS/8)/256;          // 34816
  const int wBlocks = (NW*(WSZ/8))/256;        // 4480
  cvtAll<<<xBlocks + wBlocks, 256>>>(x, Wq, Wkc, Wkp, Wkn, Wfp, Wfn, Wfc);

  // [1] q / kc
  hgemm_store<<<dim3(64,4,2), 256, DYN_SMEM>>>(bq, bkc, qkc);

  // [2] merged: ap/an partial dots (z 0..15) + fp/fn normalized outputs (z 16..31)
  hgemm_dn<<<dim3(64,4,32), 256, DYN_SMEM>>>(bkp, bkn, bfp, bfn, q, dotP, out);

  // [3] mix -> vh (fp16 direct)
  mix_kernel<<<Bsz, 128>>>(x, vh, q, kc, dotP);

  // [4] fc (+ residual xc), cluster-fused norm
  hgemm_fc<<<dim3(64,4,1), 256, DYN_SMEM>>>(bfc, x, out);
}